// round 1
// baseline (speedup 1.0000x reference)
#include <cuda_runtime.h>
#include <math_constants.h>

#define D_MODEL 1024
#define N_HEAD 16
#define HEAD_DIM 64
#define BATCH 2
#define SEQ 2048
#define M_TOTAL (BATCH * SEQ)

// Scratch (allocation-free: __device__ globals)
__device__ float g_qh[(size_t)BATCH * N_HEAD * SEQ * HEAD_DIM];
__device__ float g_kh[(size_t)BATCH * N_HEAD * SEQ * HEAD_DIM];
__device__ float g_vh[(size_t)BATCH * N_HEAD * SEQ * HEAD_DIM];
__device__ float g_attn[(size_t)M_TOTAL * D_MODEL];

// ---------------------------------------------------------------------------
// 128x128x16 SGEMM core, 256 threads, 8x8 per thread.
// mode 0: dst[m*D_MODEL + n] (flat row-major)
// mode 1: head-split dst[((batch*16+h)*SEQ + s)*64 + d]
// ---------------------------------------------------------------------------
__device__ __forceinline__ void gemm_128x128(
    const float* __restrict__ A, const float* __restrict__ W,
    const float* __restrict__ bias, float* __restrict__ dst, int mode)
{
    __shared__ float As[16][128];   // As[k][m] (transposed A tile)
    __shared__ float Bs[16][128];   // Bs[k][n]

    const int tid = threadIdx.x;
    const int tx = tid & 15;        // n direction
    const int ty = tid >> 4;        // m direction
    const int bm = blockIdx.y * 128;
    const int bn = blockIdx.x * 128;

    float acc[8][8];
#pragma unroll
    for (int i = 0; i < 8; i++)
#pragma unroll
        for (int j = 0; j < 8; j++) acc[i][j] = 0.0f;

    const float* Ab = A + (size_t)bm * D_MODEL;
    const float* Wb = W + bn;

    for (int k0 = 0; k0 < D_MODEL; k0 += 16) {
        // Load A tile 128(m) x 16(k): 512 float4, 2 per thread, store transposed
#pragma unroll
        for (int it = 0; it < 2; it++) {
            int idx = tid * 2 + it;
            int row = idx >> 2;      // 0..127
            int c4  = idx & 3;       // 0..3 (float4 within the 16 k's)
            float4 av = *(const float4*)(Ab + (size_t)row * D_MODEL + k0 + c4 * 4);
            As[c4 * 4 + 0][row] = av.x;
            As[c4 * 4 + 1][row] = av.y;
            As[c4 * 4 + 2][row] = av.z;
            As[c4 * 4 + 3][row] = av.w;
        }
        // Load B tile 16(k) x 128(n): coalesced float4
#pragma unroll
        for (int it = 0; it < 2; it++) {
            int idx = tid * 2 + it;
            int r  = idx >> 5;       // 0..15
            int c4 = idx & 31;       // 0..31
            *(float4*)(&Bs[r][c4 * 4]) =
                *(const float4*)(Wb + (size_t)(k0 + r) * D_MODEL + c4 * 4);
        }
        __syncthreads();

#pragma unroll
        for (int kk = 0; kk < 16; kk++) {
            float a[8], b[8];
            *(float4*)(a)     = *(const float4*)(&As[kk][ty * 4]);
            *(float4*)(a + 4) = *(const float4*)(&As[kk][64 + ty * 4]);
            *(float4*)(b)     = *(const float4*)(&Bs[kk][tx * 4]);
            *(float4*)(b + 4) = *(const float4*)(&Bs[kk][64 + tx * 4]);
#pragma unroll
            for (int i = 0; i < 8; i++)
#pragma unroll
                for (int j = 0; j < 8; j++)
                    acc[i][j] += a[i] * b[j];
        }
        __syncthreads();
    }

    // Epilogue: bias add + store (float4)
#pragma unroll
    for (int hi = 0; hi < 2; hi++)
#pragma unroll
        for (int i = 0; i < 4; i++) {
            int m = bm + hi * 64 + ty * 4 + i;
#pragma unroll
            for (int hj = 0; hj < 2; hj++) {
                int n = bn + hj * 64 + tx * 4;
                float4 r;
                r.x = acc[hi * 4 + i][hj * 4 + 0] + bias[n + 0];
                r.y = acc[hi * 4 + i][hj * 4 + 1] + bias[n + 1];
                r.z = acc[hi * 4 + i][hj * 4 + 2] + bias[n + 2];
                r.w = acc[hi * 4 + i][hj * 4 + 3] + bias[n + 3];
                if (mode == 0) {
                    *(float4*)(dst + (size_t)m * D_MODEL + n) = r;
                } else {
                    int batch = m >> 11;       // m / SEQ
                    int s     = m & 2047;      // m % SEQ
                    int h     = n >> 6;        // n / HEAD_DIM
                    int d     = n & 63;        // n % HEAD_DIM
                    size_t o = (((size_t)(batch * N_HEAD + h) * SEQ + s) << 6) + d;
                    *(float4*)(dst + o) = r;
                }
            }
        }
}

__global__ __launch_bounds__(256) void qkv_gemm_kernel(
    const float* __restrict__ q, const float* __restrict__ k, const float* __restrict__ v,
    const float* __restrict__ Wq, const float* __restrict__ Wk, const float* __restrict__ Wv,
    const float* __restrict__ bq, const float* __restrict__ bk, const float* __restrict__ bv)
{
    int z = blockIdx.z;
    const float* A = (z == 0) ? q  : (z == 1) ? k  : v;
    const float* W = (z == 0) ? Wq : (z == 1) ? Wk : Wv;
    const float* b = (z == 0) ? bq : (z == 1) ? bk : bv;
    float* dst     = (z == 0) ? g_qh : (z == 1) ? g_kh : g_vh;
    gemm_128x128(A, W, b, dst, 1);
}

__global__ __launch_bounds__(256) void out_gemm_kernel(
    const float* __restrict__ Wo, const float* __restrict__ bo, float* __restrict__ out)
{
    gemm_128x128(g_attn, Wo, bo, out, 0);
}

// ---------------------------------------------------------------------------
// Flash attention: one CTA = 64 queries of one (batch, head); loops 64 tiles
// of 32 keys. 256 threads as 16(ty: q-groups) x 16(tx: key/dim lanes).
// Per thread: 4 q-rows; scores for keys {tx, tx+16}; PV cols {tx*4..tx*4+3}.
// Writes directly into head-concat layout g_attn[m][n].
// ---------------------------------------------------------------------------
__global__ __launch_bounds__(256) void attn_kernel()
{
    __shared__ float Qs[64][64];    // [q][d]
    __shared__ float Ks[32][68];    // [key][d], padded
    __shared__ float Vs[32][68];    // [key][d], padded
    __shared__ float Pt[32][68];    // P transposed: [key][q], padded (16B-aligned rows)

    const int tid = threadIdx.x;
    const int tx = tid & 15;
    const int ty = tid >> 4;
    const int qb = blockIdx.x;      // 0..31 query blocks
    const int bh = blockIdx.y;      // 0..31 (batch*head)
    const int batch = bh >> 4;
    const int h = bh & 15;

    const float* Qg  = g_qh + ((size_t)bh * SEQ + qb * 64) * HEAD_DIM;
    const float* Kg0 = g_kh + (size_t)bh * SEQ * HEAD_DIM;
    const float* Vg0 = g_vh + (size_t)bh * SEQ * HEAD_DIM;

    // Load Q block 64x64 (1024 float4)
#pragma unroll
    for (int i = 0; i < 4; i++) {
        int idx = i * 256 + tid;
        int row = idx >> 4, c4 = idx & 15;
        *(float4*)(&Qs[row][c4 * 4]) = *(const float4*)(Qg + row * 64 + c4 * 4);
    }

    float m_i[4], l_i[4], acc[4][4];
#pragma unroll
    for (int i = 0; i < 4; i++) {
        m_i[i] = -CUDART_INF_F;
        l_i[i] = 0.0f;
#pragma unroll
        for (int j = 0; j < 4; j++) acc[i][j] = 0.0f;
    }
    __syncthreads();

    for (int kt = 0; kt < SEQ / 32; kt++) {
        const float* Kg = Kg0 + kt * 32 * 64;
        const float* Vg = Vg0 + kt * 32 * 64;
#pragma unroll
        for (int i = 0; i < 2; i++) {
            int idx = i * 256 + tid;
            int row = idx >> 4, c4 = idx & 15;
            *(float4*)(&Ks[row][c4 * 4]) = *(const float4*)(Kg + row * 64 + c4 * 4);
            *(float4*)(&Vs[row][c4 * 4]) = *(const float4*)(Vg + row * 64 + c4 * 4);
        }
        __syncthreads();

        // Scores: s[i][j] = Q[ty*4+i][:] . K[tx + 16j][:]
        float s[4][2] = {{0, 0}, {0, 0}, {0, 0}, {0, 0}};
#pragma unroll
        for (int d4 = 0; d4 < 16; d4++) {
            float4 kv0 = *(const float4*)(&Ks[tx][d4 * 4]);
            float4 kv1 = *(const float4*)(&Ks[tx + 16][d4 * 4]);
#pragma unroll
            for (int i = 0; i < 4; i++) {
                float4 qv = *(const float4*)(&Qs[ty * 4 + i][d4 * 4]);
                s[i][0] += qv.x * kv0.x + qv.y * kv0.y + qv.z * kv0.z + qv.w * kv0.w;
                s[i][1] += qv.x * kv1.x + qv.y * kv1.y + qv.z * kv1.z + qv.w * kv1.w;
            }
        }

        // Online softmax update + stage P transposed
#pragma unroll
        for (int i = 0; i < 4; i++) {
            float s0 = s[i][0] * 0.125f;   // 1/sqrt(64)
            float s1 = s[i][1] * 0.125f;
            float mt = fmaxf(s0, s1);
#pragma unroll
            for (int o = 8; o; o >>= 1)
                mt = fmaxf(mt, __shfl_xor_sync(0xffffffffu, mt, o, 16));
            float mn = fmaxf(m_i[i], mt);
            float alpha = __expf(m_i[i] - mn);   // first tile: exp(-inf)=0
            m_i[i] = mn;
            float p0 = __expf(s0 - mn);
            float p1 = __expf(s1 - mn);
            float lt = p0 + p1;
#pragma unroll
            for (int o = 8; o; o >>= 1)
                lt += __shfl_xor_sync(0xffffffffu, lt, o, 16);
            l_i[i] = l_i[i] * alpha + lt;
#pragma unroll
            for (int jj = 0; jj < 4; jj++) acc[i][jj] *= alpha;
            Pt[tx][ty * 4 + i]      = p0;
            Pt[tx + 16][ty * 4 + i] = p1;
        }
        __syncthreads();

        // PV: acc[i][jj] += sum_k Pt[k][ty*4+i] * Vs[k][tx*4+jj]
#pragma unroll
        for (int k = 0; k < 32; k++) {
            float4 pv = *(const float4*)(&Pt[k][ty * 4]);
            float4 vv = *(const float4*)(&Vs[k][tx * 4]);
            float pa[4] = {pv.x, pv.y, pv.z, pv.w};
#pragma unroll
            for (int i = 0; i < 4; i++) {
                acc[i][0] += pa[i] * vv.x;
                acc[i][1] += pa[i] * vv.y;
                acc[i][2] += pa[i] * vv.z;
                acc[i][3] += pa[i] * vv.w;
            }
        }
        __syncthreads();
    }

    // Finalize + write head-concat layout
#pragma unroll
    for (int i = 0; i < 4; i++) {
        float inv = 1.0f / l_i[i];
        int m = batch * SEQ + qb * 64 + ty * 4 + i;
        int n = h * HEAD_DIM + tx * 4;
        float4 r;
        r.x = acc[i][0] * inv;
        r.y = acc[i][1] * inv;
        r.z = acc[i][2] * inv;
        r.w = acc[i][3] * inv;
        *(float4*)(g_attn + (size_t)m * D_MODEL + n) = r;
    }
}

// ---------------------------------------------------------------------------
extern "C" void kernel_launch(void* const* d_in, const int* in_sizes, int n_in,
                              void* d_out, int out_size)
{
    const float* q  = (const float*)d_in[0];
    const float* k  = (const float*)d_in[1];
    const float* v  = (const float*)d_in[2];
    const float* Wq = (const float*)d_in[3];
    const float* bq = (const float*)d_in[4];
    const float* Wk = (const float*)d_in[5];
    const float* bk = (const float*)d_in[6];
    const float* Wv = (const float*)d_in[7];
    const float* bv = (const float*)d_in[8];
    const float* Wo = (const float*)d_in[9];
    const float* bo = (const float*)d_in[10];
    float* out = (float*)d_out;

    dim3 g_qkv(D_MODEL / 128, M_TOTAL / 128, 3);   // (8, 32, 3)
    qkv_gemm_kernel<<<g_qkv, 256>>>(q, k, v, Wq, Wk, Wv, bq, bk, bv);

    dim3 g_att(SEQ / 64, BATCH * N_HEAD);          // (32, 32)
    attn_kernel<<<g_att, 256>>>();

    dim3 g_out(D_MODEL / 128, M_TOTAL / 128);      // (8, 32)
    out_gemm_kernel<<<g_out, 256>>>(Wo, bo, out);
}

// round 3
// speedup vs baseline: 2.1445x; 2.1445x over previous
#include <cuda_runtime.h>
#include <math_constants.h>
#include <cstdint>

#define D_MODEL 1024
#define N_HEAD 16
#define HEAD_DIM 64
#define BATCH 2
#define SEQ 2048
#define M_TOTAL (BATCH * SEQ)

// ---------------- scratch (allocation-free) ----------------
__device__ float g_qh[(size_t)BATCH * N_HEAD * SEQ * HEAD_DIM];
__device__ float g_kh[(size_t)BATCH * N_HEAD * SEQ * HEAD_DIM];
__device__ float g_vh[(size_t)BATCH * N_HEAD * SEQ * HEAD_DIM];
__device__ float g_attn[(size_t)M_TOTAL * D_MODEL];

// ---------------- helpers ----------------
__device__ __forceinline__ uint32_t tf32r(float x) {
    uint32_t u;
    asm("cvt.rna.tf32.f32 %0, %1;" : "=r"(u) : "f"(x));
    return u;
}

// D += A(16x8) * B(8x8), tf32 inputs, f32 accum.
__device__ __forceinline__ void mma8(float* d, const uint32_t* a, const uint32_t* b) {
    asm volatile(
        "mma.sync.aligned.m16n8k8.row.col.f32.tf32.tf32.f32 "
        "{%0,%1,%2,%3}, {%4,%5,%6,%7}, {%8,%9}, {%0,%1,%2,%3};"
        : "+f"(d[0]), "+f"(d[1]), "+f"(d[2]), "+f"(d[3])
        : "r"(a[0]), "r"(a[1]), "r"(a[2]), "r"(a[3]), "r"(b[0]), "r"(b[1]));
}

// =====================================================================
// GEMM: C[4096x1024] = A[4096x1024] @ W[1024x1024] + bias
// 128x128 CTA tile, BK=32, double-buffered smem, 8 warps (32x64 each).
// =====================================================================
#define BK 32
#define NITER (D_MODEL / BK)
#define APAD 36    // words per A smem row  (bank: 4g+tig bijective)
#define BPAD 136   // words per B smem row  (bank: 8tig+g bijective)
#define GEMM_SMEM_WORDS (2 * 128 * APAD + 2 * 32 * BPAD)
#define GEMM_SMEM_BYTES (GEMM_SMEM_WORDS * 4)

__device__ __forceinline__ void ldg_gemm(const float* __restrict__ A,
                                         const float* __restrict__ W,
                                         int bm, int bn, int k0, int tid,
                                         float* fa, float* fw) {
#pragma unroll
    for (int t = 0; t < 4; t++) {
        int id = tid + t * 256;
        int row = id >> 3, c4 = id & 7;
        float4 v = *(const float4*)(A + (size_t)(bm + row) * D_MODEL + k0 + c4 * 4);
        fa[t * 4 + 0] = v.x; fa[t * 4 + 1] = v.y; fa[t * 4 + 2] = v.z; fa[t * 4 + 3] = v.w;
    }
#pragma unroll
    for (int t = 0; t < 4; t++) {
        int id = tid + t * 256;
        int k = id >> 5, c4 = id & 31;
        float4 v = *(const float4*)(W + (size_t)(k0 + k) * D_MODEL + bn + c4 * 4);
        fw[t * 4 + 0] = v.x; fw[t * 4 + 1] = v.y; fw[t * 4 + 2] = v.z; fw[t * 4 + 3] = v.w;
    }
}

__device__ __forceinline__ void sts_gemm(uint32_t* as, uint32_t* bs, int tid,
                                         const float* fa, const float* fw) {
#pragma unroll
    for (int t = 0; t < 4; t++) {
        int id = tid + t * 256;
        int row = id >> 3, c4 = id & 7;
        uint32_t* p = as + row * APAD + c4 * 4;
        p[0] = tf32r(fa[t * 4 + 0]); p[1] = tf32r(fa[t * 4 + 1]);
        p[2] = tf32r(fa[t * 4 + 2]); p[3] = tf32r(fa[t * 4 + 3]);
    }
#pragma unroll
    for (int t = 0; t < 4; t++) {
        int id = tid + t * 256;
        int k = id >> 5, c4 = id & 31;
        uint32_t* p = bs + k * BPAD + c4 * 4;
        p[0] = tf32r(fw[t * 4 + 0]); p[1] = tf32r(fw[t * 4 + 1]);
        p[2] = tf32r(fw[t * 4 + 2]); p[3] = tf32r(fw[t * 4 + 3]);
    }
}

// mode 0: dst[m][n] flat; mode 1: head-split [((b*16+h)*SEQ+s)*64+d]
__device__ __forceinline__ void gemm_tc(const float* __restrict__ A,
                                        const float* __restrict__ W,
                                        const float* __restrict__ bias,
                                        float* __restrict__ dst, int mode) {
    extern __shared__ uint32_t sm[];
    uint32_t* As[2] = { sm, sm + 128 * APAD };
    uint32_t* Bs[2] = { sm + 2 * 128 * APAD, sm + 2 * 128 * APAD + 32 * BPAD };

    const int tid = threadIdx.x;
    const int lane = tid & 31, w = tid >> 5;
    const int g = lane >> 2, tig = lane & 3;
    const int wm = w & 3, wn = w >> 2;
    const int bm = blockIdx.y * 128, bn = blockIdx.x * 128;

    float acc[2][8][4];
#pragma unroll
    for (int i = 0; i < 2; i++)
#pragma unroll
        for (int j = 0; j < 8; j++)
#pragma unroll
            for (int r = 0; r < 4; r++) acc[i][j][r] = 0.0f;

    float fa[16], fw[16];
    ldg_gemm(A, W, bm, bn, 0, tid, fa, fw);
    sts_gemm(As[0], Bs[0], tid, fa, fw);
    __syncthreads();

#pragma unroll 1
    for (int j = 0; j < NITER; j++) {
        int buf = j & 1;
        if (j + 1 < NITER) ldg_gemm(A, W, bm, bn, (j + 1) * BK, tid, fa, fw);

        const uint32_t* as = As[buf];
        const uint32_t* bs = Bs[buf];
#pragma unroll
        for (int ks = 0; ks < 4; ks++) {
            uint32_t af[2][4], bf[8][2];
#pragma unroll
            for (int am = 0; am < 2; am++) {
                int r = wm * 32 + am * 16 + g;
                int c = ks * 8 + tig;
                af[am][0] = as[r * APAD + c];
                af[am][1] = as[(r + 8) * APAD + c];
                af[am][2] = as[r * APAD + c + 4];
                af[am][3] = as[(r + 8) * APAD + c + 4];
            }
#pragma unroll
            for (int an = 0; an < 8; an++) {
                int n = wn * 64 + an * 8 + g;
                int kk = ks * 8 + tig;
                bf[an][0] = bs[kk * BPAD + n];
                bf[an][1] = bs[(kk + 4) * BPAD + n];
            }
#pragma unroll
            for (int am = 0; am < 2; am++)
#pragma unroll
                for (int an = 0; an < 8; an++)
                    mma8(acc[am][an], af[am], bf[an]);
        }

        if (j + 1 < NITER) sts_gemm(As[buf ^ 1], Bs[buf ^ 1], tid, fa, fw);
        __syncthreads();
    }

    // epilogue
#pragma unroll
    for (int am = 0; am < 2; am++)
#pragma unroll
        for (int an = 0; an < 8; an++) {
            int r = bm + wm * 32 + am * 16 + g;
            int n = bn + wn * 64 + an * 8 + 2 * tig;
            float b0 = bias[n], b1 = bias[n + 1];
            float2 v0 = { acc[am][an][0] + b0, acc[am][an][1] + b1 };
            float2 v1 = { acc[am][an][2] + b0, acc[am][an][3] + b1 };
            if (mode == 0) {
                *(float2*)(dst + (size_t)r * D_MODEL + n) = v0;
                *(float2*)(dst + (size_t)(r + 8) * D_MODEL + n) = v1;
            } else {
                int h = n >> 6, d = n & 63;
                int b = r >> 11, s = r & 2047;
                *(float2*)(dst + ((((size_t)b * N_HEAD + h) * SEQ + s) << 6) + d) = v0;
                int s1 = (r + 8) & 2047, b1i = (r + 8) >> 11;
                *(float2*)(dst + ((((size_t)b1i * N_HEAD + h) * SEQ + s1) << 6) + d) = v1;
            }
        }
}

__global__ __launch_bounds__(256, 1)
void qkv_gemm_kernel(const float* __restrict__ q, const float* __restrict__ k,
                     const float* __restrict__ v,
                     const float* __restrict__ Wq, const float* __restrict__ Wk,
                     const float* __restrict__ Wv,
                     const float* __restrict__ bq, const float* __restrict__ bk,
                     const float* __restrict__ bv) {
    int z = blockIdx.z;
    const float* A = (z == 0) ? q : (z == 1) ? k : v;
    const float* W = (z == 0) ? Wq : (z == 1) ? Wk : Wv;
    const float* b = (z == 0) ? bq : (z == 1) ? bk : bv;
    float* dst = (z == 0) ? g_qh : (z == 1) ? g_kh : g_vh;
    gemm_tc(A, W, b, dst, 1);
}

__global__ __launch_bounds__(256, 1)
void out_gemm_kernel(const float* __restrict__ Wo, const float* __restrict__ bo,
                     float* __restrict__ out) {
    gemm_tc(g_attn, Wo, bo, out, 0);
}

// =====================================================================
// Flash attention with tf32 mma. CTA: 128 q-rows of one (b,h).
// 8 warps x 16 q-rows. 64-key tiles, online softmax in registers.
// =====================================================================
#define QP 68   // bank: 4g+tig bijective for A-frag
#define KP 68   // bank: 4g+tig bijective for K b-frag (key indexed by g)
#define VP 72   // bank: 8tig+g bijective for V b-frag (key indexed by tig)
#define PP 68
#define ATTN_SMEM_WORDS (128 * QP + 64 * KP + 64 * VP + 128 * PP)
#define ATTN_SMEM_BYTES (ATTN_SMEM_WORDS * 4)

__global__ __launch_bounds__(256, 1) void attn_kernel() {
    extern __shared__ uint32_t sm[];
    uint32_t* Qs = sm;
    uint32_t* Ks = Qs + 128 * QP;
    uint32_t* Vs = Ks + 64 * KP;
    uint32_t* Ps = Vs + 64 * VP;

    const int tid = threadIdx.x;
    const int lane = tid & 31, w = tid >> 5;
    const int g = lane >> 2, tig = lane & 3;
    const int qb = blockIdx.x, bh = blockIdx.y;
    const int batch = bh >> 4, h = bh & 15;

    const float* Qg = g_qh + ((size_t)bh * SEQ + qb * 128) * 64;
    const float* Kg = g_kh + (size_t)bh * SEQ * 64;
    const float* Vg = g_vh + (size_t)bh * SEQ * 64;

    // load Q (pre-scaled by 1/sqrt(64))
#pragma unroll
    for (int i = 0; i < 8; i++) {
        int id = tid + i * 256;
        int row = id >> 4, c4 = id & 15;
        float4 v = *(const float4*)(Qg + row * 64 + c4 * 4);
        uint32_t* p = Qs + row * QP + c4 * 4;
        p[0] = tf32r(v.x * 0.125f); p[1] = tf32r(v.y * 0.125f);
        p[2] = tf32r(v.z * 0.125f); p[3] = tf32r(v.w * 0.125f);
    }

    float o[8][4];
#pragma unroll
    for (int a = 0; a < 8; a++)
#pragma unroll
        for (int r = 0; r < 4; r++) o[a][r] = 0.0f;
    float m0 = -CUDART_INF_F, m1 = -CUDART_INF_F, l0 = 0.0f, l1 = 0.0f;

    const int r0 = 16 * w + g;

#pragma unroll 1
    for (int kt = 0; kt < SEQ / 64; kt++) {
#pragma unroll
        for (int i = 0; i < 4; i++) {
            int id = tid + i * 256;
            int row = id >> 4, c4 = id & 15;
            float4 kv = *(const float4*)(Kg + (size_t)(kt * 64 + row) * 64 + c4 * 4);
            float4 vv = *(const float4*)(Vg + (size_t)(kt * 64 + row) * 64 + c4 * 4);
            uint32_t* pk = Ks + row * KP + c4 * 4;
            pk[0] = tf32r(kv.x); pk[1] = tf32r(kv.y); pk[2] = tf32r(kv.z); pk[3] = tf32r(kv.w);
            uint32_t* pv = Vs + row * VP + c4 * 4;
            pv[0] = tf32r(vv.x); pv[1] = tf32r(vv.y); pv[2] = tf32r(vv.z); pv[3] = tf32r(vv.w);
        }
        __syncthreads();

        // S = Q @ K^T   (16 q-rows x 64 keys per warp)
        float s[8][4];
#pragma unroll
        for (int a = 0; a < 8; a++)
#pragma unroll
            for (int r = 0; r < 4; r++) s[a][r] = 0.0f;

#pragma unroll
        for (int ks = 0; ks < 8; ks++) {
            int c = ks * 8 + tig;
            uint32_t af[4];
            af[0] = Qs[r0 * QP + c];
            af[1] = Qs[(r0 + 8) * QP + c];
            af[2] = Qs[r0 * QP + c + 4];
            af[3] = Qs[(r0 + 8) * QP + c + 4];
#pragma unroll
            for (int an = 0; an < 8; an++) {
                int key = an * 8 + g;
                uint32_t bf[2];
                bf[0] = Ks[key * KP + c];
                bf[1] = Ks[key * KP + c + 4];
                mma8(s[an], af, bf);
            }
        }

        // online softmax (rows r0, r0+8)
        float mx0 = -CUDART_INF_F, mx1 = -CUDART_INF_F;
#pragma unroll
        for (int an = 0; an < 8; an++) {
            mx0 = fmaxf(mx0, fmaxf(s[an][0], s[an][1]));
            mx1 = fmaxf(mx1, fmaxf(s[an][2], s[an][3]));
        }
        mx0 = fmaxf(mx0, __shfl_xor_sync(0xffffffffu, mx0, 1));
        mx0 = fmaxf(mx0, __shfl_xor_sync(0xffffffffu, mx0, 2));
        mx1 = fmaxf(mx1, __shfl_xor_sync(0xffffffffu, mx1, 1));
        mx1 = fmaxf(mx1, __shfl_xor_sync(0xffffffffu, mx1, 2));
        float mn0 = fmaxf(m0, mx0), mn1 = fmaxf(m1, mx1);
        float al0 = __expf(m0 - mn0), al1 = __expf(m1 - mn1);
        m0 = mn0; m1 = mn1;

        float la0 = 0.0f, la1 = 0.0f;
#pragma unroll
        for (int an = 0; an < 8; an++) {
            float p00 = __expf(s[an][0] - mn0);
            float p01 = __expf(s[an][1] - mn0);
            float p10 = __expf(s[an][2] - mn1);
            float p11 = __expf(s[an][3] - mn1);
            la0 += p00 + p01;
            la1 += p10 + p11;
            int cc = an * 8 + 2 * tig;
            Ps[r0 * PP + cc] = tf32r(p00);
            Ps[r0 * PP + cc + 1] = tf32r(p01);
            Ps[(r0 + 8) * PP + cc] = tf32r(p10);
            Ps[(r0 + 8) * PP + cc + 1] = tf32r(p11);
        }
        l0 = l0 * al0 + la0;
        l1 = l1 * al1 + la1;
#pragma unroll
        for (int an = 0; an < 8; an++) {
            o[an][0] *= al0; o[an][1] *= al0;
            o[an][2] *= al1; o[an][3] *= al1;
        }
        __syncwarp();   // P rows are warp-private

        // O += P @ V
#pragma unroll
        for (int ks = 0; ks < 8; ks++) {
            int c = ks * 8 + tig;
            uint32_t af[4];
            af[0] = Ps[r0 * PP + c];
            af[1] = Ps[(r0 + 8) * PP + c];
            af[2] = Ps[r0 * PP + c + 4];
            af[3] = Ps[(r0 + 8) * PP + c + 4];
#pragma unroll
            for (int an = 0; an < 8; an++) {
                uint32_t bf[2];
                bf[0] = Vs[(ks * 8 + tig) * VP + an * 8 + g];
                bf[1] = Vs[(ks * 8 + tig + 4) * VP + an * 8 + g];
                mma8(o[an], af, bf);
            }
        }
        __syncthreads();
    }

    // finalize
    l0 += __shfl_xor_sync(0xffffffffu, l0, 1);
    l0 += __shfl_xor_sync(0xffffffffu, l0, 2);
    l1 += __shfl_xor_sync(0xffffffffu, l1, 1);
    l1 += __shfl_xor_sync(0xffffffffu, l1, 2);
    float inv0 = 1.0f / l0, inv1 = 1.0f / l1;

    int mrow = batch * SEQ + qb * 128 + 16 * w + g;
#pragma unroll
    for (int an = 0; an < 8; an++) {
        int d = an * 8 + 2 * tig;
        float2 v0 = { o[an][0] * inv0, o[an][1] * inv0 };
        float2 v1 = { o[an][2] * inv1, o[an][3] * inv1 };
        *(float2*)(g_attn + (size_t)mrow * D_MODEL + h * 64 + d) = v0;
        *(float2*)(g_attn + (size_t)(mrow + 8) * D_MODEL + h * 64 + d) = v1;
    }
}

// ---------------------------------------------------------------------------
extern "C" void kernel_launch(void* const* d_in, const int* in_sizes, int n_in,
                              void* d_out, int out_size) {
    const float* q  = (const float*)d_in[0];
    const float* k  = (const float*)d_in[1];
    const float* v  = (const float*)d_in[2];
    const float* Wq = (const float*)d_in[3];
    const float* bq = (const float*)d_in[4];
    const float* Wk = (const float*)d_in[5];
    const float* bk = (const float*)d_in[6];
    const float* Wv = (const float*)d_in[7];
    const float* bv = (const float*)d_in[8];
    const float* Wo = (const float*)d_in[9];
    const float* bo = (const float*)d_in[10];
    float* out = (float*)d_out;

    cudaFuncSetAttribute(qkv_gemm_kernel, cudaFuncAttributeMaxDynamicSharedMemorySize, GEMM_SMEM_BYTES);
    cudaFuncSetAttribute(out_gemm_kernel, cudaFuncAttributeMaxDynamicSharedMemorySize, GEMM_SMEM_BYTES);
    cudaFuncSetAttribute(attn_kernel,     cudaFuncAttributeMaxDynamicSharedMemorySize, ATTN_SMEM_BYTES);

    dim3 g_qkv(D_MODEL / 128, M_TOTAL / 128, 3);   // (8, 32, 3)
    qkv_gemm_kernel<<<g_qkv, 256, GEMM_SMEM_BYTES>>>(q, k, v, Wq, Wk, Wv, bq, bk, bv);

    dim3 g_att(SEQ / 128, BATCH * N_HEAD);         // (16, 32)
    attn_kernel<<<g_att, 256, ATTN_SMEM_BYTES>>>();

    dim3 g_out(D_MODEL / 128, M_TOTAL / 128);      // (8, 32)
    out_gemm_kernel<<<g_out, 256, GEMM_SMEM_BYTES>>>(Wo, bo, out);
}

// round 4
// speedup vs baseline: 2.9404x; 1.3711x over previous
#include <cuda_runtime.h>
#include <math_constants.h>
#include <cstdint>

#define D_MODEL 1024
#define N_HEAD 16
#define HEAD_DIM 64
#define BATCH 2
#define SEQ 2048
#define M_TOTAL (BATCH * SEQ)

// ---------------- scratch (allocation-free __device__ globals) ----------------
__device__ float g_qh[(size_t)BATCH * N_HEAD * SEQ * HEAD_DIM];
__device__ float g_kh[(size_t)BATCH * N_HEAD * SEQ * HEAD_DIM];
__device__ float g_vh[(size_t)BATCH * N_HEAD * SEQ * HEAD_DIM];
__device__ float g_attn[(size_t)M_TOTAL * D_MODEL];
// tf32-pre-rounded copies of external inputs
__device__ float g_rq[(size_t)M_TOTAL * D_MODEL];
__device__ float g_rk[(size_t)M_TOTAL * D_MODEL];
__device__ float g_rv[(size_t)M_TOTAL * D_MODEL];
__device__ float g_rwq[(size_t)D_MODEL * D_MODEL];
__device__ float g_rwk[(size_t)D_MODEL * D_MODEL];
__device__ float g_rwv[(size_t)D_MODEL * D_MODEL];
__device__ float g_rwo[(size_t)D_MODEL * D_MODEL];

// ---------------- helpers ----------------
__device__ __forceinline__ uint32_t tf32r(float x) {
    uint32_t u;
    asm("cvt.rna.tf32.f32 %0, %1;" : "=r"(u) : "f"(x));
    return u;
}
__device__ __forceinline__ uint32_t smem_u32(const void* p) {
    uint32_t a;
    asm("{ .reg .u64 t; cvta.to.shared.u64 t, %1; cvt.u32.u64 %0, t; }" : "=r"(a) : "l"(p));
    return a;
}
__device__ __forceinline__ void cpa16(uint32_t saddr, const void* g) {
    asm volatile("cp.async.cg.shared.global [%0], [%1], 16;" :: "r"(saddr), "l"(g));
}
__device__ __forceinline__ void cp_commit() {
    asm volatile("cp.async.commit_group;" ::: "memory");
}
template <int N> __device__ __forceinline__ void cp_wait() {
    asm volatile("cp.async.wait_group %0;" :: "n"(N) : "memory");
}

// D += A(16x8) * B(8x8), tf32 inputs, f32 accum.
__device__ __forceinline__ void mma8(float* d, const uint32_t* a, const uint32_t* b) {
    asm volatile(
        "mma.sync.aligned.m16n8k8.row.col.f32.tf32.tf32.f32 "
        "{%0,%1,%2,%3}, {%4,%5,%6,%7}, {%8,%9}, {%0,%1,%2,%3};"
        : "+f"(d[0]), "+f"(d[1]), "+f"(d[2]), "+f"(d[3])
        : "r"(a[0]), "r"(a[1]), "r"(a[2]), "r"(a[3]), "r"(b[0]), "r"(b[1]));
}

// =====================================================================
// Prepass: round external inputs to tf32 once.
// =====================================================================
__global__ __launch_bounds__(256) void round_pass_kernel(
    const float* __restrict__ q, const float* __restrict__ k, const float* __restrict__ v,
    const float* __restrict__ wq, const float* __restrict__ wk,
    const float* __restrict__ wv, const float* __restrict__ wo) {
    int z = blockIdx.z;
    const float* src;
    float* dst;
    int nf4;
    switch (z) {
        case 0: src = q;  dst = g_rq;  nf4 = (M_TOTAL * D_MODEL) / 4; break;
        case 1: src = k;  dst = g_rk;  nf4 = (M_TOTAL * D_MODEL) / 4; break;
        case 2: src = v;  dst = g_rv;  nf4 = (M_TOTAL * D_MODEL) / 4; break;
        case 3: src = wq; dst = g_rwq; nf4 = (D_MODEL * D_MODEL) / 4; break;
        case 4: src = wk; dst = g_rwk; nf4 = (D_MODEL * D_MODEL) / 4; break;
        case 5: src = wv; dst = g_rwv; nf4 = (D_MODEL * D_MODEL) / 4; break;
        default: src = wo; dst = g_rwo; nf4 = (D_MODEL * D_MODEL) / 4; break;
    }
    for (int i = blockIdx.x * blockDim.x + threadIdx.x; i < nf4;
         i += gridDim.x * blockDim.x) {
        float4 x = ((const float4*)src)[i];
        uint4 r;
        r.x = tf32r(x.x); r.y = tf32r(x.y); r.z = tf32r(x.z); r.w = tf32r(x.w);
        ((uint4*)dst)[i] = r;
    }
}

// =====================================================================
// GEMM: C[4096x1024] = A @ W + bias. 128x128 tile, BK=32, cp.async x2.
// Inputs MUST be pre-rounded tf32 bit patterns.
// =====================================================================
#define BK 32
#define NITER (D_MODEL / BK)
#define APAD 36     // words/row for A smem (bank 4g+tig bijective; 144B = 16B mult)
#define BPAD 136    // words/row for B smem (bank 8tig+g bijective; 544B = 16B mult)
#define GEMM_SMEM_WORDS (2 * 128 * APAD + 2 * 32 * BPAD)
#define GEMM_SMEM_BYTES (GEMM_SMEM_WORDS * 4)   // 71680

__device__ __forceinline__ void gemm_stage(const float* __restrict__ A,
                                           const float* __restrict__ W,
                                           int bm, int bn, int k0, int tid,
                                           uint32_t as_b, uint32_t bs_b) {
#pragma unroll
    for (int t = 0; t < 4; t++) {
        int id = tid + t * 256;
        int row = id >> 3, ch = id & 7;
        cpa16(as_b + (uint32_t)(row * APAD + ch * 4) * 4,
              A + (size_t)(bm + row) * D_MODEL + k0 + ch * 4);
    }
#pragma unroll
    for (int t = 0; t < 4; t++) {
        int id = tid + t * 256;
        int row = id >> 5, ch = id & 31;
        cpa16(bs_b + (uint32_t)(row * BPAD + ch * 4) * 4,
              W + (size_t)(k0 + row) * D_MODEL + bn + ch * 4);
    }
    cp_commit();
}

// mode 0: dst[m][n] flat fp32; mode 1: head-split, tf32-rounded
__device__ __forceinline__ void gemm_tc(const float* __restrict__ A,
                                        const float* __restrict__ W,
                                        const float* __restrict__ bias,
                                        float* __restrict__ dst, int mode) {
    extern __shared__ uint32_t sm[];
    uint32_t* As[2] = { sm, sm + 128 * APAD };
    uint32_t* Bs[2] = { sm + 2 * 128 * APAD, sm + 2 * 128 * APAD + 32 * BPAD };
    const uint32_t smb = smem_u32(sm);
    const uint32_t asb[2] = { smb, smb + 128 * APAD * 4 };
    const uint32_t bsb[2] = { smb + 2 * 128 * APAD * 4, smb + (2 * 128 * APAD + 32 * BPAD) * 4 };

    const int tid = threadIdx.x;
    const int lane = tid & 31, w = tid >> 5;
    const int g = lane >> 2, tig = lane & 3;
    const int wm = w & 3, wn = w >> 2;
    const int bm = blockIdx.y * 128, bn = blockIdx.x * 128;

    float acc[2][8][4];
#pragma unroll
    for (int i = 0; i < 2; i++)
#pragma unroll
        for (int j = 0; j < 8; j++)
#pragma unroll
            for (int r = 0; r < 4; r++) acc[i][j][r] = 0.0f;

    gemm_stage(A, W, bm, bn, 0, tid, asb[0], bsb[0]);

#pragma unroll 1
    for (int j = 0; j < NITER; j++) {
        int buf = j & 1;
        if (j + 1 < NITER) {
            gemm_stage(A, W, bm, bn, (j + 1) * BK, tid, asb[buf ^ 1], bsb[buf ^ 1]);
            cp_wait<1>();
        } else {
            cp_wait<0>();
        }
        __syncthreads();

        const uint32_t* as = As[buf];
        const uint32_t* bs = Bs[buf];
#pragma unroll
        for (int ks = 0; ks < 4; ks++) {
            uint32_t af[2][4], bf[8][2];
#pragma unroll
            for (int am = 0; am < 2; am++) {
                int r = wm * 32 + am * 16 + g;
                int c = ks * 8 + tig;
                af[am][0] = as[r * APAD + c];
                af[am][1] = as[(r + 8) * APAD + c];
                af[am][2] = as[r * APAD + c + 4];
                af[am][3] = as[(r + 8) * APAD + c + 4];
            }
#pragma unroll
            for (int an = 0; an < 8; an++) {
                int n = wn * 64 + an * 8 + g;
                int kk = ks * 8 + tig;
                bf[an][0] = bs[kk * BPAD + n];
                bf[an][1] = bs[(kk + 4) * BPAD + n];
            }
#pragma unroll
            for (int am = 0; am < 2; am++)
#pragma unroll
                for (int an = 0; an < 8; an++)
                    mma8(acc[am][an], af[am], bf[an]);
        }
        __syncthreads();
    }

    // epilogue
#pragma unroll
    for (int am = 0; am < 2; am++)
#pragma unroll
        for (int an = 0; an < 8; an++) {
            int r = bm + wm * 32 + am * 16 + g;
            int n = bn + wn * 64 + an * 8 + 2 * tig;
            float b0 = bias[n], b1 = bias[n + 1];
            if (mode == 0) {
                float2 v0 = { acc[am][an][0] + b0, acc[am][an][1] + b1 };
                float2 v1 = { acc[am][an][2] + b0, acc[am][an][3] + b1 };
                *(float2*)(dst + (size_t)r * D_MODEL + n) = v0;
                *(float2*)(dst + (size_t)(r + 8) * D_MODEL + n) = v1;
            } else {
                float2 v0 = { __uint_as_float(tf32r(acc[am][an][0] + b0)),
                              __uint_as_float(tf32r(acc[am][an][1] + b1)) };
                float2 v1 = { __uint_as_float(tf32r(acc[am][an][2] + b0)),
                              __uint_as_float(tf32r(acc[am][an][3] + b1)) };
                int h = n >> 6, d = n & 63;
                int b = r >> 11, s = r & 2047;
                *(float2*)(dst + ((((size_t)b * N_HEAD + h) * SEQ + s) << 6) + d) = v0;
                int s1 = (r + 8) & 2047, b1i = (r + 8) >> 11;
                *(float2*)(dst + ((((size_t)b1i * N_HEAD + h) * SEQ + s1) << 6) + d) = v1;
            }
        }
}

__global__ __launch_bounds__(256, 2)
void qkv_gemm_kernel(const float* __restrict__ bq, const float* __restrict__ bk,
                     const float* __restrict__ bv) {
    int z = blockIdx.z;
    const float* A = (z == 0) ? g_rq : (z == 1) ? g_rk : g_rv;
    const float* W = (z == 0) ? g_rwq : (z == 1) ? g_rwk : g_rwv;
    const float* b = (z == 0) ? bq : (z == 1) ? bk : bv;
    float* dst = (z == 0) ? g_qh : (z == 1) ? g_kh : g_vh;
    gemm_tc(A, W, b, dst, 1);
}

__global__ __launch_bounds__(256, 2)
void out_gemm_kernel(const float* __restrict__ bo, float* __restrict__ out) {
    gemm_tc(g_attn, g_rwo, bo, out, 0);
}

// =====================================================================
// Flash attention, tf32 mma, cp.async K/V double-buffer.
// CTA: 128 q-rows of one (b,h). 8 warps x 16 q-rows. 64-key tiles.
// Q smem region is reused as P (warp-private rows match).
// =====================================================================
#define QP 68   // also P pitch (bank 4g+tig bijective; 272B = 16B mult)
#define KP 68
#define VP 72   // (bank 8tig+g bijective; 288B = 16B mult)
#define ATTN_SMEM_WORDS (128 * QP + 2 * 64 * KP + 2 * 64 * VP)   // 26624
#define ATTN_SMEM_BYTES (ATTN_SMEM_WORDS * 4)                     // 106496

__global__ __launch_bounds__(256, 2) void attn_kernel() {
    extern __shared__ uint32_t sm[];
    uint32_t* Qs = sm;                       // becomes P after Q frags extracted
    uint32_t* Ks[2] = { sm + 128 * QP, sm + 128 * QP + 64 * KP };
    uint32_t* Vs[2] = { sm + 128 * QP + 2 * 64 * KP,
                        sm + 128 * QP + 2 * 64 * KP + 64 * VP };
    const uint32_t smb = smem_u32(sm);
    const uint32_t qsb = smb;
    const uint32_t ksb[2] = { smb + 128 * QP * 4, smb + (128 * QP + 64 * KP) * 4 };
    const uint32_t vsb[2] = { smb + (128 * QP + 2 * 64 * KP) * 4,
                              smb + (128 * QP + 2 * 64 * KP + 64 * VP) * 4 };

    const int tid = threadIdx.x;
    const int lane = tid & 31, w = tid >> 5;
    const int g = lane >> 2, tig = lane & 3;
    const int qb = blockIdx.x, bh = blockIdx.y;
    const int batch = bh >> 4, h = bh & 15;
    const int r0 = 16 * w + g;

    const float* Qg = g_qh + ((size_t)bh * SEQ + qb * 128) * 64;
    const float* Kg = g_kh + (size_t)bh * SEQ * 64;
    const float* Vg = g_vh + (size_t)bh * SEQ * 64;

    // group 0: Q + K0 + V0
#pragma unroll
    for (int t = 0; t < 8; t++) {
        int id = tid + t * 256;
        int row = id >> 4, ch = id & 15;
        cpa16(qsb + (uint32_t)(row * QP + ch * 4) * 4, Qg + row * 64 + ch * 4);
    }
#pragma unroll
    for (int t = 0; t < 4; t++) {
        int id = tid + t * 256;
        int row = id >> 4, ch = id & 15;
        cpa16(ksb[0] + (uint32_t)(row * KP + ch * 4) * 4, Kg + (size_t)row * 64 + ch * 4);
        cpa16(vsb[0] + (uint32_t)(row * VP + ch * 4) * 4, Vg + (size_t)row * 64 + ch * 4);
    }
    cp_commit();

    uint32_t qf[8][4];
    float o[8][4];
#pragma unroll
    for (int a = 0; a < 8; a++)
#pragma unroll
        for (int r = 0; r < 4; r++) o[a][r] = 0.0f;
    float m0 = -CUDART_INF_F, m1 = -CUDART_INF_F, l0 = 0.0f, l1 = 0.0f;

#pragma unroll 1
    for (int kt = 0; kt < SEQ / 64; kt++) {
        int buf = kt & 1;
        if (kt + 1 < SEQ / 64) {
#pragma unroll
            for (int t = 0; t < 4; t++) {
                int id = tid + t * 256;
                int row = id >> 4, ch = id & 15;
                cpa16(ksb[buf ^ 1] + (uint32_t)(row * KP + ch * 4) * 4,
                      Kg + (size_t)((kt + 1) * 64 + row) * 64 + ch * 4);
                cpa16(vsb[buf ^ 1] + (uint32_t)(row * VP + ch * 4) * 4,
                      Vg + (size_t)((kt + 1) * 64 + row) * 64 + ch * 4);
            }
            cp_commit();
            cp_wait<1>();
        } else {
            cp_wait<0>();
        }
        __syncthreads();

        if (kt == 0) {
#pragma unroll
            for (int ks = 0; ks < 8; ks++) {
                int c = ks * 8 + tig;
                qf[ks][0] = Qs[r0 * QP + c];
                qf[ks][1] = Qs[(r0 + 8) * QP + c];
                qf[ks][2] = Qs[r0 * QP + c + 4];
                qf[ks][3] = Qs[(r0 + 8) * QP + c + 4];
            }
        }

        // S = Q @ K^T
        float s[8][4];
#pragma unroll
        for (int a = 0; a < 8; a++)
#pragma unroll
            for (int r = 0; r < 4; r++) s[a][r] = 0.0f;
        const uint32_t* ks_p = Ks[buf];
#pragma unroll
        for (int ks = 0; ks < 8; ks++) {
            int c = ks * 8 + tig;
#pragma unroll
            for (int an = 0; an < 8; an++) {
                int key = an * 8 + g;
                uint32_t bf[2];
                bf[0] = ks_p[key * KP + c];
                bf[1] = ks_p[key * KP + c + 4];
                mma8(s[an], qf[ks], bf);
            }
        }

        // online softmax (scale 1/sqrt(64) applied here)
        float mx0 = -CUDART_INF_F, mx1 = -CUDART_INF_F;
#pragma unroll
        for (int an = 0; an < 8; an++) {
            s[an][0] *= 0.125f; s[an][1] *= 0.125f;
            s[an][2] *= 0.125f; s[an][3] *= 0.125f;
            mx0 = fmaxf(mx0, fmaxf(s[an][0], s[an][1]));
            mx1 = fmaxf(mx1, fmaxf(s[an][2], s[an][3]));
        }
        mx0 = fmaxf(mx0, __shfl_xor_sync(0xffffffffu, mx0, 1));
        mx0 = fmaxf(mx0, __shfl_xor_sync(0xffffffffu, mx0, 2));
        mx1 = fmaxf(mx1, __shfl_xor_sync(0xffffffffu, mx1, 1));
        mx1 = fmaxf(mx1, __shfl_xor_sync(0xffffffffu, mx1, 2));
        float mn0 = fmaxf(m0, mx0), mn1 = fmaxf(m1, mx1);
        float al0 = __expf(m0 - mn0), al1 = __expf(m1 - mn1);
        m0 = mn0; m1 = mn1;

        float la0 = 0.0f, la1 = 0.0f;
#pragma unroll
        for (int an = 0; an < 8; an++) {
            float p00 = __expf(s[an][0] - mn0);
            float p01 = __expf(s[an][1] - mn0);
            float p10 = __expf(s[an][2] - mn1);
            float p11 = __expf(s[an][3] - mn1);
            la0 += p00 + p01;
            la1 += p10 + p11;
            int cc = an * 8 + 2 * tig;
            Qs[r0 * QP + cc] = tf32r(p00);
            Qs[r0 * QP + cc + 1] = tf32r(p01);
            Qs[(r0 + 8) * QP + cc] = tf32r(p10);
            Qs[(r0 + 8) * QP + cc + 1] = tf32r(p11);
        }
        l0 = l0 * al0 + la0;
        l1 = l1 * al1 + la1;
#pragma unroll
        for (int an = 0; an < 8; an++) {
            o[an][0] *= al0; o[an][1] *= al0;
            o[an][2] *= al1; o[an][3] *= al1;
        }
        __syncwarp();   // P rows are warp-private

        // O += P @ V
        const uint32_t* vs_p = Vs[buf];
#pragma unroll
        for (int ks = 0; ks < 8; ks++) {
            int c = ks * 8 + tig;
            uint32_t af[4];
            af[0] = Qs[r0 * QP + c];
            af[1] = Qs[(r0 + 8) * QP + c];
            af[2] = Qs[r0 * QP + c + 4];
            af[3] = Qs[(r0 + 8) * QP + c + 4];
#pragma unroll
            for (int an = 0; an < 8; an++) {
                uint32_t bf[2];
                bf[0] = vs_p[(ks * 8 + tig) * VP + an * 8 + g];
                bf[1] = vs_p[(ks * 8 + tig + 4) * VP + an * 8 + g];
                mma8(o[an], af, bf);
            }
        }
        __syncthreads();
    }

    // finalize (store tf32-rounded for the out-proj cp.async path)
    l0 += __shfl_xor_sync(0xffffffffu, l0, 1);
    l0 += __shfl_xor_sync(0xffffffffu, l0, 2);
    l1 += __shfl_xor_sync(0xffffffffu, l1, 1);
    l1 += __shfl_xor_sync(0xffffffffu, l1, 2);
    float inv0 = 1.0f / l0, inv1 = 1.0f / l1;

    int mrow = batch * SEQ + qb * 128 + 16 * w + g;
#pragma unroll
    for (int an = 0; an < 8; an++) {
        int d = an * 8 + 2 * tig;
        float2 v0 = { __uint_as_float(tf32r(o[an][0] * inv0)),
                      __uint_as_float(tf32r(o[an][1] * inv0)) };
        float2 v1 = { __uint_as_float(tf32r(o[an][2] * inv1)),
                      __uint_as_float(tf32r(o[an][3] * inv1)) };
        *(float2*)(g_attn + (size_t)mrow * D_MODEL + h * 64 + d) = v0;
        *(float2*)(g_attn + (size_t)(mrow + 8) * D_MODEL + h * 64 + d) = v1;
    }
}

// ---------------------------------------------------------------------------
extern "C" void kernel_launch(void* const* d_in, const int* in_sizes, int n_in,
                              void* d_out, int out_size) {
    const float* q  = (const float*)d_in[0];
    const float* k  = (const float*)d_in[1];
    const float* v  = (const float*)d_in[2];
    const float* Wq = (const float*)d_in[3];
    const float* bq = (const float*)d_in[4];
    const float* Wk = (const float*)d_in[5];
    const float* bk = (const float*)d_in[6];
    const float* Wv = (const float*)d_in[7];
    const float* bv = (const float*)d_in[8];
    const float* Wo = (const float*)d_in[9];
    const float* bo = (const float*)d_in[10];
    float* out = (float*)d_out;

    cudaFuncSetAttribute(qkv_gemm_kernel, cudaFuncAttributeMaxDynamicSharedMemorySize, GEMM_SMEM_BYTES);
    cudaFuncSetAttribute(out_gemm_kernel, cudaFuncAttributeMaxDynamicSharedMemorySize, GEMM_SMEM_BYTES);
    cudaFuncSetAttribute(attn_kernel,     cudaFuncAttributeMaxDynamicSharedMemorySize, ATTN_SMEM_BYTES);

    dim3 g_round(512, 1, 7);
    round_pass_kernel<<<g_round, 256>>>(q, k, v, Wq, Wk, Wv, Wo);

    dim3 g_qkv(D_MODEL / 128, M_TOTAL / 128, 3);   // (8, 32, 3)
    qkv_gemm_kernel<<<g_qkv, 256, GEMM_SMEM_BYTES>>>(bq, bk, bv);

    dim3 g_att(SEQ / 128, BATCH * N_HEAD);         // (16, 32)
    attn_kernel<<<g_att, 256, ATTN_SMEM_BYTES>>>();

    dim3 g_out(D_MODEL / 128, M_TOTAL / 128);      // (8, 32)
    out_gemm_kernel<<<g_out, 256, GEMM_SMEM_BYTES>>>(bo, out);
}

// round 5
// speedup vs baseline: 3.7400x; 1.2719x over previous
#include <cuda_runtime.h>
#include <math_constants.h>
#include <cstdint>

#define D_MODEL 1024
#define N_HEAD 16
#define HEAD_DIM 64
#define BATCH 2
#define SEQ 2048
#define M_TOTAL (BATCH * SEQ)

// ---------------- scratch (allocation-free __device__ globals) ----------------
__device__ float g_qh[(size_t)BATCH * N_HEAD * SEQ * HEAD_DIM];   // [bh][s][d]
__device__ float g_kh[(size_t)BATCH * N_HEAD * SEQ * HEAD_DIM];   // [bh][s][d]
__device__ float g_vt[(size_t)BATCH * N_HEAD * HEAD_DIM * SEQ];   // [bh][d][s]  (transposed V)
__device__ float g_attn[(size_t)M_TOTAL * D_MODEL];
// tf32-pre-rounded copies of inputs; weights stored TRANSPOSED [n][k]
__device__ float g_rq[(size_t)M_TOTAL * D_MODEL];
__device__ float g_rk[(size_t)M_TOTAL * D_MODEL];
__device__ float g_rv[(size_t)M_TOTAL * D_MODEL];
__device__ float g_twq[(size_t)D_MODEL * D_MODEL];
__device__ float g_twk[(size_t)D_MODEL * D_MODEL];
__device__ float g_twv[(size_t)D_MODEL * D_MODEL];
__device__ float g_two[(size_t)D_MODEL * D_MODEL];

// ---------------- helpers ----------------
__device__ __forceinline__ uint32_t tf32r(float x) {
    uint32_t u;
    asm("cvt.rna.tf32.f32 %0, %1;" : "=r"(u) : "f"(x));
    return u;
}
__device__ __forceinline__ uint32_t smem_u32(const void* p) {
    uint32_t a;
    asm("{ .reg .u64 t; cvta.to.shared.u64 t, %1; cvt.u32.u64 %0, t; }" : "=r"(a) : "l"(p));
    return a;
}
__device__ __forceinline__ void cpa16(uint32_t saddr, const void* g) {
    asm volatile("cp.async.cg.shared.global [%0], [%1], 16;" :: "r"(saddr), "l"(g));
}
__device__ __forceinline__ void cp_commit() {
    asm volatile("cp.async.commit_group;" ::: "memory");
}
template <int N> __device__ __forceinline__ void cp_wait() {
    asm volatile("cp.async.wait_group %0;" :: "n"(N) : "memory");
}
// ldmatrix x4: thread lane semantics give fragment reg k = 8x4-f32 tile k, lane L -> [L/4][L%4]
__device__ __forceinline__ void ldsm4(uint32_t* r, uint32_t saddr) {
    asm volatile("ldmatrix.sync.aligned.m8n8.x4.shared.b16 {%0,%1,%2,%3}, [%4];"
                 : "=r"(r[0]), "=r"(r[1]), "=r"(r[2]), "=r"(r[3]) : "r"(saddr));
}
// D += A(16x8) * B(8x8), tf32, f32 accum
__device__ __forceinline__ void mma8(float* d, const uint32_t* a, uint32_t b0, uint32_t b1) {
    asm volatile(
        "mma.sync.aligned.m16n8k8.row.col.f32.tf32.tf32.f32 "
        "{%0,%1,%2,%3}, {%4,%5,%6,%7}, {%8,%9}, {%0,%1,%2,%3};"
        : "+f"(d[0]), "+f"(d[1]), "+f"(d[2]), "+f"(d[3])
        : "r"(a[0]), "r"(a[1]), "r"(a[2]), "r"(a[3]), "r"(b0), "r"(b1));
}

// =====================================================================
// Prepass 1: round q/k/v to tf32.
// =====================================================================
__global__ __launch_bounds__(256) void round_pass_kernel(
    const float* __restrict__ q, const float* __restrict__ k, const float* __restrict__ v) {
    int z = blockIdx.z;
    const float* src = (z == 0) ? q : (z == 1) ? k : v;
    float* dst = (z == 0) ? g_rq : (z == 1) ? g_rk : g_rv;
    int nf4 = (M_TOTAL * D_MODEL) / 4;
    for (int i = blockIdx.x * blockDim.x + threadIdx.x; i < nf4; i += gridDim.x * blockDim.x) {
        float4 x = ((const float4*)src)[i];
        uint4 r;
        r.x = tf32r(x.x); r.y = tf32r(x.y); r.z = tf32r(x.z); r.w = tf32r(x.w);
        ((uint4*)dst)[i] = r;
    }
}

// Prepass 2: transpose + round weights: Wt[n][k] = tf32(W[k][n])
__global__ __launch_bounds__(256) void wtrans_kernel(
    const float* __restrict__ wq, const float* __restrict__ wk,
    const float* __restrict__ wv, const float* __restrict__ wo) {
    __shared__ float t[32][33];
    int z = blockIdx.z;
    const float* src = (z == 0) ? wq : (z == 1) ? wk : (z == 2) ? wv : wo;
    float* dst = (z == 0) ? g_twq : (z == 1) ? g_twk : (z == 2) ? g_twv : g_two;
    int bk = blockIdx.x * 32, bn = blockIdx.y * 32;
    int tx = threadIdx.x & 31, ty = threadIdx.x >> 5;   // 32 x 8
#pragma unroll
    for (int i = 0; i < 4; i++)
        t[ty + 8 * i][tx] = src[(size_t)(bk + ty + 8 * i) * D_MODEL + bn + tx];
    __syncthreads();
#pragma unroll
    for (int i = 0; i < 4; i++)
        dst[(size_t)(bn + ty + 8 * i) * D_MODEL + bk + tx] =
            __uint_as_float(tf32r(t[tx][ty + 8 * i]));
}

// =====================================================================
// GEMM: C[4096x1024] = A @ W + bias. 128x128 tile, BK=32, 3-stage cp.async.
// A row-major [m][k]; W provided TRANSPOSED [n][k]. LDSM fragment loads.
// =====================================================================
#define BK 32
#define NITER (D_MODEL / BK)
#define APAD 36           // words/row (144B; LDSM rows conflict-free)
#define BTP 36
#define AB_OFF (128 * APAD * 4)
#define STAGE_BYTES ((128 * APAD + 128 * BTP) * 4)   // 36864
#define NSTAGE 3
#define GEMM_SMEM_BYTES (NSTAGE * STAGE_BYTES)        // 110592

__device__ __forceinline__ void gemm_stage(const float* __restrict__ A,
                                           const float* __restrict__ Wt,
                                           int bm, int bn, int k0, int tid, uint32_t sb) {
#pragma unroll
    for (int t = 0; t < 4; t++) {
        int id = tid + t * 256;
        int row = id >> 3, ch = id & 7;
        cpa16(sb + (uint32_t)(row * APAD + ch * 4) * 4,
              A + (size_t)(bm + row) * D_MODEL + k0 + ch * 4);
    }
#pragma unroll
    for (int t = 0; t < 4; t++) {
        int id = tid + t * 256;
        int row = id >> 3, ch = id & 7;
        cpa16(sb + AB_OFF + (uint32_t)(row * BTP + ch * 4) * 4,
              Wt + (size_t)(bn + row) * D_MODEL + k0 + ch * 4);
    }
    cp_commit();
}

// mode 0: dst[m][n] fp32; mode 1: head-split [bh][s][d] tf32; mode 2: V transposed [bh][d][s] tf32
__device__ __forceinline__ void gemm_tc(const float* __restrict__ A,
                                        const float* __restrict__ Wt,
                                        const float* __restrict__ bias,
                                        float* __restrict__ dst, int mode) {
    extern __shared__ uint32_t sm[];
    const uint32_t smb = smem_u32(sm);

    const int tid = threadIdx.x;
    const int lane = tid & 31, w = tid >> 5;
    const int g = lane >> 2, tig = lane & 3;
    const int wm = w & 3, wn = w >> 2;
    const int bm = blockIdx.y * 128, bn = blockIdx.x * 128;

    // per-thread LDSM byte offsets (within a stage)
    const int Lr = lane & 15;
    const int chalf = (lane >> 4) * 4;
    uint32_t aoff[2];
#pragma unroll
    for (int am = 0; am < 2; am++)
        aoff[am] = (uint32_t)((wm * 32 + am * 16 + Lr) * APAD + chalf) * 4;
    const int j3 = lane >> 3, rB = lane & 7;
    uint32_t boff[4];
#pragma unroll
    for (int p = 0; p < 4; p++)
        boff[p] = AB_OFF +
            (uint32_t)((wn * 64 + (2 * p + (j3 >> 1)) * 8 + rB) * BTP + (j3 & 1) * 4) * 4;

    float acc[2][8][4];
#pragma unroll
    for (int i = 0; i < 2; i++)
#pragma unroll
        for (int j = 0; j < 8; j++)
#pragma unroll
            for (int r = 0; r < 4; r++) acc[i][j][r] = 0.0f;

    gemm_stage(A, Wt, bm, bn, 0, tid, smb);
    gemm_stage(A, Wt, bm, bn, BK, tid, smb + STAGE_BYTES);

    int sidx = 0;
#pragma unroll 1
    for (int j = 0; j < NITER; j++) {
        if (j == NITER - 1) cp_wait<0>(); else cp_wait<1>();
        __syncthreads();
        uint32_t sb = smb + sidx * STAGE_BYTES;

#pragma unroll
        for (int ks = 0; ks < 4; ks++) {
            uint32_t af[2][4], bq[4][4];
            ldsm4(af[0], sb + aoff[0] + ks * 32);
            ldsm4(af[1], sb + aoff[1] + ks * 32);
#pragma unroll
            for (int p = 0; p < 4; p++) ldsm4(bq[p], sb + boff[p] + ks * 32);
#pragma unroll
            for (int am = 0; am < 2; am++)
#pragma unroll
                for (int p = 0; p < 4; p++) {
                    mma8(acc[am][2 * p],     af[am], bq[p][0], bq[p][1]);
                    mma8(acc[am][2 * p + 1], af[am], bq[p][2], bq[p][3]);
                }
        }

        if (j + 2 < NITER) {
            int ns = sidx + 2; if (ns >= NSTAGE) ns -= NSTAGE;
            gemm_stage(A, Wt, bm, bn, (j + 2) * BK, tid, smb + ns * STAGE_BYTES);
        }
        sidx++; if (sidx == NSTAGE) sidx = 0;
    }

    // epilogue
#pragma unroll
    for (int am = 0; am < 2; am++)
#pragma unroll
        for (int an = 0; an < 8; an++) {
            int r = bm + wm * 32 + am * 16 + g;
            int n = bn + wn * 64 + an * 8 + 2 * tig;
            float b0 = bias[n], b1 = bias[n + 1];
            if (mode == 0) {
                float2 v0 = { acc[am][an][0] + b0, acc[am][an][1] + b1 };
                float2 v1 = { acc[am][an][2] + b0, acc[am][an][3] + b1 };
                *(float2*)(dst + (size_t)r * D_MODEL + n) = v0;
                *(float2*)(dst + (size_t)(r + 8) * D_MODEL + n) = v1;
            } else if (mode == 1) {
                float2 v0 = { __uint_as_float(tf32r(acc[am][an][0] + b0)),
                              __uint_as_float(tf32r(acc[am][an][1] + b1)) };
                float2 v1 = { __uint_as_float(tf32r(acc[am][an][2] + b0)),
                              __uint_as_float(tf32r(acc[am][an][3] + b1)) };
                int h = n >> 6, d = n & 63;
                int b = r >> 11, s = r & 2047;
                *(float2*)(dst + ((((size_t)b * N_HEAD + h) * SEQ + s) << 6) + d) = v0;
                int s1 = (r + 8) & 2047, b1i = (r + 8) >> 11;
                *(float2*)(dst + ((((size_t)b1i * N_HEAD + h) * SEQ + s1) << 6) + d) = v1;
            } else {
                // V transposed: [bh][d][s]
                int h = n >> 6, d = n & 63;
                int b = r >> 11, s = r & 2047;
                size_t base = ((size_t)(b * N_HEAD + h) * HEAD_DIM + d) * SEQ;
                dst[base + s]       = __uint_as_float(tf32r(acc[am][an][0] + b0));
                dst[base + SEQ + s] = __uint_as_float(tf32r(acc[am][an][1] + b1));
                int s1 = (r + 8) & 2047, b1i = (r + 8) >> 11;
                size_t base1 = ((size_t)(b1i * N_HEAD + h) * HEAD_DIM + d) * SEQ;
                dst[base1 + s1]       = __uint_as_float(tf32r(acc[am][an][2] + b0));
                dst[base1 + SEQ + s1] = __uint_as_float(tf32r(acc[am][an][3] + b1));
            }
        }
}

__global__ __launch_bounds__(256, 2)
void qkv_gemm_kernel(const float* __restrict__ bq, const float* __restrict__ bk,
                     const float* __restrict__ bv) {
    int z = blockIdx.z;
    const float* A  = (z == 0) ? g_rq  : (z == 1) ? g_rk  : g_rv;
    const float* Wt = (z == 0) ? g_twq : (z == 1) ? g_twk : g_twv;
    const float* b  = (z == 0) ? bq : (z == 1) ? bk : bv;
    float* dst      = (z == 0) ? g_qh : (z == 1) ? g_kh : g_vt;
    gemm_tc(A, Wt, b, dst, (z == 2) ? 2 : 1);
}

__global__ __launch_bounds__(256, 2)
void out_gemm_kernel(const float* __restrict__ bo, float* __restrict__ out) {
    gemm_tc(g_attn, g_two, bo, out, 0);
}

// =====================================================================
// Flash attention, tf32 mma + LDSM everywhere.
// CTA: 128 q-rows of one (b,h). 8 warps x 16 q. 64-key tiles, 2-stage.
// Q smem reused as P. V is pre-transposed [d][s] in global.
// =====================================================================
#define QP 68
#define KP 68
#define VP 68
#define ATTN_SMEM_WORDS (128 * QP + 2 * 64 * KP + 2 * 64 * VP)
#define ATTN_SMEM_BYTES (ATTN_SMEM_WORDS * 4)   // 104448

__global__ __launch_bounds__(256, 2) void attn_kernel() {
    extern __shared__ uint32_t sm[];
    const uint32_t smb = smem_u32(sm);
    const uint32_t qsb = smb;
    const uint32_t ksb[2] = { smb + 128 * QP * 4, smb + (128 * QP + 64 * KP) * 4 };
    const uint32_t vsb[2] = { smb + (128 * QP + 2 * 64 * KP) * 4,
                              smb + (128 * QP + 2 * 64 * KP + 64 * VP) * 4 };

    const int tid = threadIdx.x;
    const int lane = tid & 31, w = tid >> 5;
    const int tig = lane & 3;
    const int qb = blockIdx.x, bh = blockIdx.y;
    const int batch = bh >> 4, h = bh & 15;

    const float* Qg = g_qh + ((size_t)bh * SEQ + qb * 128) * 64;
    const float* Kg = g_kh + (size_t)bh * SEQ * 64;
    const float* Vg = g_vt + (size_t)bh * HEAD_DIM * SEQ;

    // LDSM per-thread offsets
    const int Lr = lane & 15, chalf = (lane >> 4) * 4;
    const uint32_t qoff = (uint32_t)((16 * w + Lr) * QP + chalf) * 4;
    const int j3 = lane >> 3, rB = lane & 7;
    uint32_t koff[4], voff[4];
#pragma unroll
    for (int p = 0; p < 4; p++) {
        int rown = (2 * p + (j3 >> 1)) * 8 + rB;
        koff[p] = (uint32_t)(rown * KP + (j3 & 1) * 4) * 4;
        voff[p] = (uint32_t)(rown * VP + (j3 & 1) * 4) * 4;
    }

    // stage group 0: Q + K0 + V0
#pragma unroll
    for (int t = 0; t < 8; t++) {
        int id = tid + t * 256;
        int row = id >> 4, ch = id & 15;
        cpa16(qsb + (uint32_t)(row * QP + ch * 4) * 4, Qg + row * 64 + ch * 4);
    }
#pragma unroll
    for (int t = 0; t < 4; t++) {
        int id = tid + t * 256;
        int row = id >> 4, ch = id & 15;
        cpa16(ksb[0] + (uint32_t)(row * KP + ch * 4) * 4, Kg + (size_t)row * 64 + ch * 4);
        cpa16(vsb[0] + (uint32_t)(row * VP + ch * 4) * 4, Vg + (size_t)row * SEQ + ch * 4);
    }
    cp_commit();

    uint32_t qf[8][4];
    float o[8][4];
#pragma unroll
    for (int a = 0; a < 8; a++)
#pragma unroll
        for (int r = 0; r < 4; r++) o[a][r] = 0.0f;
    float m0 = -CUDART_INF_F, m1 = -CUDART_INF_F, l0 = 0.0f, l1 = 0.0f;
    const int r0 = 16 * w + (lane >> 2);

#pragma unroll 1
    for (int kt = 0; kt < SEQ / 64; kt++) {
        int buf = kt & 1;
        if (kt + 1 < SEQ / 64) {
#pragma unroll
            for (int t = 0; t < 4; t++) {
                int id = tid + t * 256;
                int row = id >> 4, ch = id & 15;
                cpa16(ksb[buf ^ 1] + (uint32_t)(row * KP + ch * 4) * 4,
                      Kg + (size_t)((kt + 1) * 64 + row) * 64 + ch * 4);
                cpa16(vsb[buf ^ 1] + (uint32_t)(row * VP + ch * 4) * 4,
                      Vg + (size_t)row * SEQ + (kt + 1) * 64 + ch * 4);
            }
            cp_commit();
            cp_wait<1>();
        } else {
            cp_wait<0>();
        }
        __syncthreads();

        if (kt == 0) {
#pragma unroll
            for (int ks = 0; ks < 8; ks++) ldsm4(qf[ks], qsb + qoff + ks * 32);
        }

        // S = Q @ K^T
        float s[8][4];
#pragma unroll
        for (int a = 0; a < 8; a++)
#pragma unroll
            for (int r = 0; r < 4; r++) s[a][r] = 0.0f;
#pragma unroll
        for (int ks = 0; ks < 8; ks++) {
#pragma unroll
            for (int p = 0; p < 4; p++) {
                uint32_t bq[4];
                ldsm4(bq, ksb[buf] + koff[p] + ks * 32);
                mma8(s[2 * p],     qf[ks], bq[0], bq[1]);
                mma8(s[2 * p + 1], qf[ks], bq[2], bq[3]);
            }
        }

        // online softmax
        float mx0 = -CUDART_INF_F, mx1 = -CUDART_INF_F;
#pragma unroll
        for (int an = 0; an < 8; an++) {
            s[an][0] *= 0.125f; s[an][1] *= 0.125f;
            s[an][2] *= 0.125f; s[an][3] *= 0.125f;
            mx0 = fmaxf(mx0, fmaxf(s[an][0], s[an][1]));
            mx1 = fmaxf(mx1, fmaxf(s[an][2], s[an][3]));
        }
        mx0 = fmaxf(mx0, __shfl_xor_sync(0xffffffffu, mx0, 1));
        mx0 = fmaxf(mx0, __shfl_xor_sync(0xffffffffu, mx0, 2));
        mx1 = fmaxf(mx1, __shfl_xor_sync(0xffffffffu, mx1, 1));
        mx1 = fmaxf(mx1, __shfl_xor_sync(0xffffffffu, mx1, 2));
        float mn0 = fmaxf(m0, mx0), mn1 = fmaxf(m1, mx1);
        float al0 = __expf(m0 - mn0), al1 = __expf(m1 - mn1);
        m0 = mn0; m1 = mn1;

        float la0 = 0.0f, la1 = 0.0f;
        uint32_t* Ps = sm;   // reuse Q region
#pragma unroll
        for (int an = 0; an < 8; an++) {
            float p00 = __expf(s[an][0] - mn0);
            float p01 = __expf(s[an][1] - mn0);
            float p10 = __expf(s[an][2] - mn1);
            float p11 = __expf(s[an][3] - mn1);
            la0 += p00 + p01;
            la1 += p10 + p11;
            int cc = an * 8 + 2 * tig;
            uint2 w0 = { tf32r(p00), tf32r(p01) };
            uint2 w1 = { tf32r(p10), tf32r(p11) };
            *(uint2*)(Ps + r0 * QP + cc) = w0;
            *(uint2*)(Ps + (r0 + 8) * QP + cc) = w1;
        }
        l0 = l0 * al0 + la0;
        l1 = l1 * al1 + la1;
#pragma unroll
        for (int an = 0; an < 8; an++) {
            o[an][0] *= al0; o[an][1] *= al0;
            o[an][2] *= al1; o[an][3] *= al1;
        }
        __syncwarp();   // P rows are warp-private

        // O += P @ V
#pragma unroll
        for (int ks = 0; ks < 8; ks++) {
            uint32_t af[4];
            ldsm4(af, qsb + qoff + ks * 32);
#pragma unroll
            for (int p = 0; p < 4; p++) {
                uint32_t bv[4];
                ldsm4(bv, vsb[buf] + voff[p] + ks * 32);
                mma8(o[2 * p],     af, bv[0], bv[1]);
                mma8(o[2 * p + 1], af, bv[2], bv[3]);
            }
        }
        __syncthreads();
    }

    // finalize (tf32-rounded for out-proj LDSM path)
    l0 += __shfl_xor_sync(0xffffffffu, l0, 1);
    l0 += __shfl_xor_sync(0xffffffffu, l0, 2);
    l1 += __shfl_xor_sync(0xffffffffu, l1, 1);
    l1 += __shfl_xor_sync(0xffffffffu, l1, 2);
    float inv0 = 1.0f / l0, inv1 = 1.0f / l1;

    int mrow = batch * SEQ + qb * 128 + r0;
#pragma unroll
    for (int an = 0; an < 8; an++) {
        int d = an * 8 + 2 * tig;
        float2 v0 = { __uint_as_float(tf32r(o[an][0] * inv0)),
                      __uint_as_float(tf32r(o[an][1] * inv0)) };
        float2 v1 = { __uint_as_float(tf32r(o[an][2] * inv1)),
                      __uint_as_float(tf32r(o[an][3] * inv1)) };
        *(float2*)(g_attn + (size_t)mrow * D_MODEL + h * 64 + d) = v0;
        *(float2*)(g_attn + (size_t)(mrow + 8) * D_MODEL + h * 64 + d) = v1;
    }
}

// ---------------------------------------------------------------------------
extern "C" void kernel_launch(void* const* d_in, const int* in_sizes, int n_in,
                              void* d_out, int out_size) {
    const float* q  = (const float*)d_in[0];
    const float* k  = (const float*)d_in[1];
    const float* v  = (const float*)d_in[2];
    const float* Wq = (const float*)d_in[3];
    const float* bq = (const float*)d_in[4];
    const float* Wk = (const float*)d_in[5];
    const float* bk = (const float*)d_in[6];
    const float* Wv = (const float*)d_in[7];
    const float* bv = (const float*)d_in[8];
    const float* Wo = (const float*)d_in[9];
    const float* bo = (const float*)d_in[10];
    float* out = (float*)d_out;

    cudaFuncSetAttribute(qkv_gemm_kernel, cudaFuncAttributeMaxDynamicSharedMemorySize, GEMM_SMEM_BYTES);
    cudaFuncSetAttribute(out_gemm_kernel, cudaFuncAttributeMaxDynamicSharedMemorySize, GEMM_SMEM_BYTES);
    cudaFuncSetAttribute(attn_kernel,     cudaFuncAttributeMaxDynamicSharedMemorySize, ATTN_SMEM_BYTES);

    dim3 g_round(512, 1, 3);
    round_pass_kernel<<<g_round, 256>>>(q, k, v);

    dim3 g_wt(D_MODEL / 32, D_MODEL / 32, 4);
    wtrans_kernel<<<g_wt, 256>>>(Wq, Wk, Wv, Wo);

    dim3 g_qkv(D_MODEL / 128, M_TOTAL / 128, 3);   // (8, 32, 3)
    qkv_gemm_kernel<<<g_qkv, 256, GEMM_SMEM_BYTES>>>(bq, bk, bv);

    dim3 g_att(SEQ / 128, BATCH * N_HEAD);         // (16, 32)
    attn_kernel<<<g_att, 256, ATTN_SMEM_BYTES>>>();

    dim3 g_out(D_MODEL / 128, M_TOTAL / 128);      // (8, 32)
    out_gemm_kernel<<<g_out, 256, GEMM_SMEM_BYTES>>>(bo, out);
}

// round 6
// speedup vs baseline: 6.5205x; 1.7434x over previous
#include <cuda_runtime.h>
#include <cuda_fp16.h>
#include <math_constants.h>
#include <cstdint>

#define D_MODEL 1024
#define N_HEAD 16
#define HEAD_DIM 64
#define BATCH 2
#define SEQ 2048
#define M_TOTAL (BATCH * SEQ)

// ---------------- scratch (allocation-free __device__ globals) ----------------
__device__ __half g_hq[(size_t)M_TOTAL * D_MODEL];    // fp16 inputs
__device__ __half g_hk[(size_t)M_TOTAL * D_MODEL];
__device__ __half g_hv[(size_t)M_TOTAL * D_MODEL];
__device__ __half g_twq[(size_t)D_MODEL * D_MODEL];   // fp16 weights, transposed [n][k]
__device__ __half g_twk[(size_t)D_MODEL * D_MODEL];
__device__ __half g_twv[(size_t)D_MODEL * D_MODEL];
__device__ __half g_two[(size_t)D_MODEL * D_MODEL];
__device__ __half g_qh[(size_t)BATCH * N_HEAD * SEQ * HEAD_DIM];   // [bh][s][d]
__device__ __half g_kh[(size_t)BATCH * N_HEAD * SEQ * HEAD_DIM];   // [bh][s][d]
__device__ __half g_vt[(size_t)BATCH * N_HEAD * HEAD_DIM * SEQ];   // [bh][d][s]
__device__ __half g_attn[(size_t)M_TOTAL * D_MODEL];               // [m][n]

// ---------------- helpers ----------------
__device__ __forceinline__ uint32_t smem_u32(const void* p) {
    uint32_t a;
    asm("{ .reg .u64 t; cvta.to.shared.u64 t, %1; cvt.u32.u64 %0, t; }" : "=r"(a) : "l"(p));
    return a;
}
__device__ __forceinline__ void cpa16(uint32_t saddr, const void* g) {
    asm volatile("cp.async.cg.shared.global [%0], [%1], 16;" :: "r"(saddr), "l"(g));
}
__device__ __forceinline__ void cp_commit() {
    asm volatile("cp.async.commit_group;" ::: "memory");
}
template <int N> __device__ __forceinline__ void cp_wait() {
    asm volatile("cp.async.wait_group %0;" :: "n"(N) : "memory");
}
__device__ __forceinline__ void ldsm4(uint32_t* r, uint32_t saddr) {
    asm volatile("ldmatrix.sync.aligned.m8n8.x4.shared.b16 {%0,%1,%2,%3}, [%4];"
                 : "=r"(r[0]), "=r"(r[1]), "=r"(r[2]), "=r"(r[3]) : "r"(saddr));
}
// D += A(16x16) * B(16x8), fp16 inputs, fp32 accum
__device__ __forceinline__ void mma16(float* d, const uint32_t* a, uint32_t b0, uint32_t b1) {
    asm volatile(
        "mma.sync.aligned.m16n8k16.row.col.f32.f16.f16.f32 "
        "{%0,%1,%2,%3}, {%4,%5,%6,%7}, {%8,%9}, {%0,%1,%2,%3};"
        : "+f"(d[0]), "+f"(d[1]), "+f"(d[2]), "+f"(d[3])
        : "r"(a[0]), "r"(a[1]), "r"(a[2]), "r"(a[3]), "r"(b0), "r"(b1));
}
__device__ __forceinline__ uint32_t h2u(float a, float b) {
    __half2 h = __floats2half2_rn(a, b);
    return *(uint32_t*)&h;
}

// =====================================================================
// Prepass 1: q/k/v fp32 -> fp16
// =====================================================================
__global__ __launch_bounds__(256) void cvt_kernel(
    const float* __restrict__ q, const float* __restrict__ k, const float* __restrict__ v) {
    int z = blockIdx.z;
    const float* src = (z == 0) ? q : (z == 1) ? k : v;
    __half* dst = (z == 0) ? g_hq : (z == 1) ? g_hk : g_hv;
    int nf4 = (M_TOTAL * D_MODEL) / 4;
    for (int i = blockIdx.x * blockDim.x + threadIdx.x; i < nf4; i += gridDim.x * blockDim.x) {
        float4 x = ((const float4*)src)[i];
        uint2 u = { h2u(x.x, x.y), h2u(x.z, x.w) };
        ((uint2*)dst)[i] = u;
    }
}

// Prepass 2: weights -> fp16, transposed: Wt[n][k] = h(W[k][n])
__global__ __launch_bounds__(256) void wtrans_kernel(
    const float* __restrict__ wq, const float* __restrict__ wk,
    const float* __restrict__ wv, const float* __restrict__ wo) {
    __shared__ float t[32][33];
    int z = blockIdx.z;
    const float* src = (z == 0) ? wq : (z == 1) ? wk : (z == 2) ? wv : wo;
    __half* dst = (z == 0) ? g_twq : (z == 1) ? g_twk : (z == 2) ? g_twv : g_two;
    int bk = blockIdx.x * 32, bn = blockIdx.y * 32;
    int tx = threadIdx.x & 31, ty = threadIdx.x >> 5;
#pragma unroll
    for (int i = 0; i < 4; i++)
        t[ty + 8 * i][tx] = src[(size_t)(bk + ty + 8 * i) * D_MODEL + bn + tx];
    __syncthreads();
#pragma unroll
    for (int i = 0; i < 4; i++)
        dst[(size_t)(bn + ty + 8 * i) * D_MODEL + bk + tx] = __float2half_rn(t[tx][ty + 8 * i]);
}

// =====================================================================
// fp16 GEMM: C[4096x1024] = A @ W + bias. 128x128 tile, BK=64, 3 stages.
// A [m][k] fp16; W transposed [n][k] fp16. LDSM + m16n8k16.
// =====================================================================
#define BK 64
#define NITER (D_MODEL / BK)
#define GPITCH 144                               // bytes per smem row (64 halfs + pad)
#define AB_OFF (128 * GPITCH)                    // 18432
#define STAGE_BYTES (2 * 128 * GPITCH)           // 36864
#define NSTAGE 3
#define GEMM_SMEM_BYTES (NSTAGE * STAGE_BYTES)   // 110592

__device__ __forceinline__ void gemm_stage(const __half* __restrict__ A,
                                           const __half* __restrict__ Wt,
                                           int bm, int bn, int k0, int tid, uint32_t sb) {
#pragma unroll
    for (int t = 0; t < 4; t++) {
        int id = tid + t * 256;
        int row = id >> 3, ch = id & 7;
        cpa16(sb + (uint32_t)(row * GPITCH + ch * 16),
              A + (size_t)(bm + row) * D_MODEL + k0 + ch * 8);
    }
#pragma unroll
    for (int t = 0; t < 4; t++) {
        int id = tid + t * 256;
        int row = id >> 3, ch = id & 7;
        cpa16(sb + AB_OFF + (uint32_t)(row * GPITCH + ch * 16),
              Wt + (size_t)(bn + row) * D_MODEL + k0 + ch * 8);
    }
    cp_commit();
}

// mode 0: fp32 flat d_out; mode 1: fp16 head-split [bh][s][d]; mode 2: fp16 V^T [bh][d][s]
__device__ __forceinline__ void gemm_tc(const __half* __restrict__ A,
                                        const __half* __restrict__ Wt,
                                        const float* __restrict__ bias,
                                        float* __restrict__ dstf, __half* __restrict__ dsth,
                                        int mode) {
    extern __shared__ uint32_t sm[];
    const uint32_t smb = smem_u32(sm);

    const int tid = threadIdx.x;
    const int lane = tid & 31, w = tid >> 5;
    const int g = lane >> 2, tig = lane & 3;
    const int wm = w & 3, wn = w >> 2;
    const int bm = blockIdx.y * 128, bn = blockIdx.x * 128;

    const int t8 = lane >> 3, lr = lane & 7;
    uint32_t aoff[2];
#pragma unroll
    for (int am = 0; am < 2; am++)
        aoff[am] = (uint32_t)((wm * 32 + am * 16 + (t8 & 1) * 8 + lr) * GPITCH + (t8 >> 1) * 16);
    uint32_t boff[4];
#pragma unroll
    for (int p = 0; p < 4; p++)
        boff[p] = AB_OFF +
            (uint32_t)((wn * 64 + p * 16 + (t8 >> 1) * 8 + lr) * GPITCH + (t8 & 1) * 16);

    float acc[2][8][4];
#pragma unroll
    for (int i = 0; i < 2; i++)
#pragma unroll
        for (int j = 0; j < 8; j++)
#pragma unroll
            for (int r = 0; r < 4; r++) acc[i][j][r] = 0.0f;

    gemm_stage(A, Wt, bm, bn, 0, tid, smb);
    gemm_stage(A, Wt, bm, bn, BK, tid, smb + STAGE_BYTES);

    int sidx = 0;
#pragma unroll 1
    for (int j = 0; j < NITER; j++) {
        if (j == NITER - 1) cp_wait<0>(); else cp_wait<1>();
        __syncthreads();
        uint32_t sb = smb + sidx * STAGE_BYTES;

#pragma unroll
        for (int ks = 0; ks < 4; ks++) {     // 4 k16-steps per BK=64
            uint32_t af[2][4];
            ldsm4(af[0], sb + aoff[0] + ks * 32);
            ldsm4(af[1], sb + aoff[1] + ks * 32);
#pragma unroll
            for (int p = 0; p < 4; p++) {
                uint32_t bq[4];
                ldsm4(bq, sb + boff[p] + ks * 32);
                mma16(acc[0][2 * p],     af[0], bq[0], bq[1]);
                mma16(acc[0][2 * p + 1], af[0], bq[2], bq[3]);
                mma16(acc[1][2 * p],     af[1], bq[0], bq[1]);
                mma16(acc[1][2 * p + 1], af[1], bq[2], bq[3]);
            }
        }

        if (j + 2 < NITER) {
            int ns = sidx + 2; if (ns >= NSTAGE) ns -= NSTAGE;
            gemm_stage(A, Wt, bm, bn, (j + 2) * BK, tid, smb + ns * STAGE_BYTES);
        }
        sidx++; if (sidx == NSTAGE) sidx = 0;
    }

    // epilogue
#pragma unroll
    for (int am = 0; am < 2; am++)
#pragma unroll
        for (int an = 0; an < 8; an++) {
            int r = bm + wm * 32 + am * 16 + g;
            int n = bn + wn * 64 + an * 8 + 2 * tig;
            float b0 = bias[n], b1 = bias[n + 1];
            float c0 = acc[am][an][0] + b0, c1 = acc[am][an][1] + b1;
            float c2 = acc[am][an][2] + b0, c3 = acc[am][an][3] + b1;
            if (mode == 0) {
                float2 v0 = { c0, c1 }, v1 = { c2, c3 };
                *(float2*)(dstf + (size_t)r * D_MODEL + n) = v0;
                *(float2*)(dstf + (size_t)(r + 8) * D_MODEL + n) = v1;
            } else if (mode == 1) {
                int h = n >> 6, d = n & 63;
                int b = r >> 11, s = r & 2047;
                *(uint32_t*)(dsth + ((((size_t)b * N_HEAD + h) * SEQ + s) << 6) + d) = h2u(c0, c1);
                int s1 = (r + 8) & 2047, b1i = (r + 8) >> 11;
                *(uint32_t*)(dsth + ((((size_t)b1i * N_HEAD + h) * SEQ + s1) << 6) + d) = h2u(c2, c3);
            } else {
                int h = n >> 6, d = n & 63;
                int b = r >> 11, s = r & 2047;
                size_t base = ((size_t)(b * N_HEAD + h) * HEAD_DIM + d) * SEQ;
                dsth[base + s]       = __float2half_rn(c0);
                dsth[base + SEQ + s] = __float2half_rn(c1);
                int s1 = (r + 8) & 2047, b1i = (r + 8) >> 11;
                size_t base1 = ((size_t)(b1i * N_HEAD + h) * HEAD_DIM + d) * SEQ;
                dsth[base1 + s1]       = __float2half_rn(c2);
                dsth[base1 + SEQ + s1] = __float2half_rn(c3);
            }
        }
}

__global__ __launch_bounds__(256, 2)
void qkv_gemm_kernel(const float* __restrict__ bq, const float* __restrict__ bk,
                     const float* __restrict__ bv) {
    int z = blockIdx.z;
    const __half* A  = (z == 0) ? g_hq  : (z == 1) ? g_hk  : g_hv;
    const __half* Wt = (z == 0) ? g_twq : (z == 1) ? g_twk : g_twv;
    const float* b   = (z == 0) ? bq : (z == 1) ? bk : bv;
    __half* dsth     = (z == 0) ? g_qh : (z == 1) ? g_kh : g_vt;
    gemm_tc(A, Wt, b, nullptr, dsth, (z == 2) ? 2 : 1);
}

__global__ __launch_bounds__(256, 2)
void out_gemm_kernel(const float* __restrict__ bo, float* __restrict__ out) {
    gemm_tc(g_attn, g_two, bo, out, nullptr, 0);
}

// =====================================================================
// Flash attention, fp16 m16n8k16. CTA: 128 q of one (b,h), 8 warps x 16 q.
// 64-key tiles, 2-stage cp.async K/V. Q smem reused as P. V^T in global.
// =====================================================================
#define APITCH 144
#define ATTN_SMEM_BYTES ((128 + 2 * 64 + 2 * 64) * APITCH)   // 55296

__global__ __launch_bounds__(256, 2) void attn_kernel() {
    extern __shared__ uint32_t sm[];
    const uint32_t smb = smem_u32(sm);
    const uint32_t qsb = smb;
    const uint32_t ksb[2] = { smb + 128 * APITCH, smb + (128 + 64) * APITCH };
    const uint32_t vsb[2] = { smb + (128 + 128) * APITCH, smb + (128 + 192) * APITCH };

    const int tid = threadIdx.x;
    const int lane = tid & 31, w = tid >> 5;
    const int g = lane >> 2, tig = lane & 3;
    const int qb = blockIdx.x, bh = blockIdx.y;
    const int batch = bh >> 4, h = bh & 15;

    const __half* Qg = g_qh + ((size_t)bh * SEQ + qb * 128) * 64;
    const __half* Kg = g_kh + (size_t)bh * SEQ * 64;
    const __half* Vg = g_vt + (size_t)bh * HEAD_DIM * SEQ;

    const int t8 = lane >> 3, lr = lane & 7;
    const uint32_t qoff = (uint32_t)((16 * w + (t8 & 1) * 8 + lr) * APITCH + (t8 >> 1) * 16);
    uint32_t bofs[4];
#pragma unroll
    for (int p = 0; p < 4; p++)
        bofs[p] = (uint32_t)((p * 16 + (t8 >> 1) * 8 + lr) * APITCH + (t8 & 1) * 16);

    // stage group 0: Q + K0 + V0
#pragma unroll
    for (int t = 0; t < 4; t++) {
        int id = tid + t * 256;
        int row = id >> 3, ch = id & 7;
        cpa16(qsb + (uint32_t)(row * APITCH + ch * 16), Qg + row * 64 + ch * 8);
    }
#pragma unroll
    for (int t = 0; t < 2; t++) {
        int id = tid + t * 256;
        int row = id >> 3, ch = id & 7;
        cpa16(ksb[0] + (uint32_t)(row * APITCH + ch * 16), Kg + (size_t)row * 64 + ch * 8);
        cpa16(vsb[0] + (uint32_t)(row * APITCH + ch * 16), Vg + (size_t)row * SEQ + ch * 8);
    }
    cp_commit();

    uint32_t qf[4][4];
    float o[8][4];
#pragma unroll
    for (int a = 0; a < 8; a++)
#pragma unroll
        for (int r = 0; r < 4; r++) o[a][r] = 0.0f;
    float m0 = -CUDART_INF_F, m1 = -CUDART_INF_F, l0 = 0.0f, l1 = 0.0f;
    const int r0 = 16 * w + g;

#pragma unroll 1
    for (int kt = 0; kt < SEQ / 64; kt++) {
        int buf = kt & 1;
        if (kt + 1 < SEQ / 64) {
#pragma unroll
            for (int t = 0; t < 2; t++) {
                int id = tid + t * 256;
                int row = id >> 3, ch = id & 7;
                cpa16(ksb[buf ^ 1] + (uint32_t)(row * APITCH + ch * 16),
                      Kg + (size_t)((kt + 1) * 64 + row) * 64 + ch * 8);
                cpa16(vsb[buf ^ 1] + (uint32_t)(row * APITCH + ch * 16),
                      Vg + (size_t)row * SEQ + (kt + 1) * 64 + ch * 8);
            }
            cp_commit();
            cp_wait<1>();
        } else {
            cp_wait<0>();
        }
        __syncthreads();

        if (kt == 0) {
#pragma unroll
            for (int ks = 0; ks < 4; ks++) ldsm4(qf[ks], qsb + qoff + ks * 32);
        }

        // S = Q @ K^T
        float s[8][4];
#pragma unroll
        for (int a = 0; a < 8; a++)
#pragma unroll
            for (int r = 0; r < 4; r++) s[a][r] = 0.0f;
#pragma unroll
        for (int ks = 0; ks < 4; ks++) {
#pragma unroll
            for (int p = 0; p < 4; p++) {
                uint32_t bq[4];
                ldsm4(bq, ksb[buf] + bofs[p] + ks * 32);
                mma16(s[2 * p],     qf[ks], bq[0], bq[1]);
                mma16(s[2 * p + 1], qf[ks], bq[2], bq[3]);
            }
        }

        // online softmax
        float mx0 = -CUDART_INF_F, mx1 = -CUDART_INF_F;
#pragma unroll
        for (int an = 0; an < 8; an++) {
            s[an][0] *= 0.125f; s[an][1] *= 0.125f;
            s[an][2] *= 0.125f; s[an][3] *= 0.125f;
            mx0 = fmaxf(mx0, fmaxf(s[an][0], s[an][1]));
            mx1 = fmaxf(mx1, fmaxf(s[an][2], s[an][3]));
        }
        mx0 = fmaxf(mx0, __shfl_xor_sync(0xffffffffu, mx0, 1));
        mx0 = fmaxf(mx0, __shfl_xor_sync(0xffffffffu, mx0, 2));
        mx1 = fmaxf(mx1, __shfl_xor_sync(0xffffffffu, mx1, 1));
        mx1 = fmaxf(mx1, __shfl_xor_sync(0xffffffffu, mx1, 2));
        float mn0 = fmaxf(m0, mx0), mn1 = fmaxf(m1, mx1);
        float al0 = __expf(m0 - mn0), al1 = __expf(m1 - mn1);
        m0 = mn0; m1 = mn1;

        float la0 = 0.0f, la1 = 0.0f;
#pragma unroll
        for (int an = 0; an < 8; an++) {
            float p00 = __expf(s[an][0] - mn0);
            float p01 = __expf(s[an][1] - mn0);
            float p10 = __expf(s[an][2] - mn1);
            float p11 = __expf(s[an][3] - mn1);
            la0 += p00 + p01;
            la1 += p10 + p11;
            // P (fp16) into Q region: row r0 / r0+8, cols an*8 + 2tig
            uint32_t off = (uint32_t)(an * 16 + tig * 4);
            *(uint32_t*)((char*)sm + r0 * APITCH + off)       = h2u(p00, p01);
            *(uint32_t*)((char*)sm + (r0 + 8) * APITCH + off) = h2u(p10, p11);
        }
        l0 = l0 * al0 + la0;
        l1 = l1 * al1 + la1;
#pragma unroll
        for (int an = 0; an < 8; an++) {
            o[an][0] *= al0; o[an][1] *= al0;
            o[an][2] *= al1; o[an][3] *= al1;
        }
        __syncwarp();   // P rows are warp-private

        // O += P @ V
#pragma unroll
        for (int ks = 0; ks < 4; ks++) {
            uint32_t pf[4];
            ldsm4(pf, qsb + qoff + ks * 32);
#pragma unroll
            for (int p = 0; p < 4; p++) {
                uint32_t bv[4];
                ldsm4(bv, vsb[buf] + bofs[p] + ks * 32);
                mma16(o[2 * p],     pf, bv[0], bv[1]);
                mma16(o[2 * p + 1], pf, bv[2], bv[3]);
            }
        }
        __syncthreads();
    }

    // finalize -> fp16 g_attn
    l0 += __shfl_xor_sync(0xffffffffu, l0, 1);
    l0 += __shfl_xor_sync(0xffffffffu, l0, 2);
    l1 += __shfl_xor_sync(0xffffffffu, l1, 1);
    l1 += __shfl_xor_sync(0xffffffffu, l1, 2);
    float inv0 = 1.0f / l0, inv1 = 1.0f / l1;

    int mrow = batch * SEQ + qb * 128 + r0;
#pragma unroll
    for (int an = 0; an < 8; an++) {
        int d = an * 8 + 2 * tig;
        *(uint32_t*)(g_attn + (size_t)mrow * D_MODEL + h * 64 + d) =
            h2u(o[an][0] * inv0, o[an][1] * inv0);
        *(uint32_t*)(g_attn + (size_t)(mrow + 8) * D_MODEL + h * 64 + d) =
            h2u(o[an][2] * inv1, o[an][3] * inv1);
    }
}

// ---------------------------------------------------------------------------
extern "C" void kernel_launch(void* const* d_in, const int* in_sizes, int n_in,
                              void* d_out, int out_size) {
    const float* q  = (const float*)d_in[0];
    const float* k  = (const float*)d_in[1];
    const float* v  = (const float*)d_in[2];
    const float* Wq = (const float*)d_in[3];
    const float* bq = (const float*)d_in[4];
    const float* Wk = (const float*)d_in[5];
    const float* bk = (const float*)d_in[6];
    const float* Wv = (const float*)d_in[7];
    const float* bv = (const float*)d_in[8];
    const float* Wo = (const float*)d_in[9];
    const float* bo = (const float*)d_in[10];
    float* out = (float*)d_out;

    cudaFuncSetAttribute(qkv_gemm_kernel, cudaFuncAttributeMaxDynamicSharedMemorySize, GEMM_SMEM_BYTES);
    cudaFuncSetAttribute(out_gemm_kernel, cudaFuncAttributeMaxDynamicSharedMemorySize, GEMM_SMEM_BYTES);
    cudaFuncSetAttribute(attn_kernel,     cudaFuncAttributeMaxDynamicSharedMemorySize, ATTN_SMEM_BYTES);

    dim3 g_cvt(512, 1, 3);
    cvt_kernel<<<g_cvt, 256>>>(q, k, v);

    dim3 g_wt(D_MODEL / 32, D_MODEL / 32, 4);
    wtrans_kernel<<<g_wt, 256>>>(Wq, Wk, Wv, Wo);

    dim3 g_qkv(D_MODEL / 128, M_TOTAL / 128, 3);   // (8, 32, 3)
    qkv_gemm_kernel<<<g_qkv, 256, GEMM_SMEM_BYTES>>>(bq, bk, bv);

    dim3 g_att(SEQ / 128, BATCH * N_HEAD);         // (16, 32)
    attn_kernel<<<g_att, 256, ATTN_SMEM_BYTES>>>();

    dim3 g_out(D_MODEL / 128, M_TOTAL / 128);      // (8, 32)
    out_gemm_kernel<<<g_out, 256, GEMM_SMEM_BYTES>>>(bo, out);
}

// round 7
// speedup vs baseline: 7.3699x; 1.1303x over previous
#include <cuda_runtime.h>
#include <cuda_fp16.h>
#include <math_constants.h>
#include <cstdint>

#define D_MODEL 1024
#define N_HEAD 16
#define HEAD_DIM 64
#define BATCH 2
#define SEQ 2048
#define M_TOTAL (BATCH * SEQ)

// 0.125 (1/sqrt(64)) * log2(e), folded into Q projection output
#define SCALE_LOG2E 0.180336880556563f

// ---------------- scratch (allocation-free __device__ globals) ----------------
__device__ __half g_hq[(size_t)M_TOTAL * D_MODEL];
__device__ __half g_hk[(size_t)M_TOTAL * D_MODEL];
__device__ __half g_hv[(size_t)M_TOTAL * D_MODEL];
__device__ __half g_twq[(size_t)D_MODEL * D_MODEL];   // weights transposed [n][k]
__device__ __half g_twk[(size_t)D_MODEL * D_MODEL];
__device__ __half g_twv[(size_t)D_MODEL * D_MODEL];
__device__ __half g_two[(size_t)D_MODEL * D_MODEL];
__device__ __half g_qh[(size_t)BATCH * N_HEAD * SEQ * HEAD_DIM];   // [bh][s][d], pre-scaled
__device__ __half g_kh[(size_t)BATCH * N_HEAD * SEQ * HEAD_DIM];   // [bh][s][d]
__device__ __half g_vt[(size_t)BATCH * N_HEAD * HEAD_DIM * SEQ];   // [bh][d][s]
__device__ __half g_attn[(size_t)M_TOTAL * D_MODEL];               // [m][n]

// ---------------- helpers ----------------
__device__ __forceinline__ uint32_t smem_u32(const void* p) {
    uint32_t a;
    asm("{ .reg .u64 t; cvta.to.shared.u64 t, %1; cvt.u32.u64 %0, t; }" : "=r"(a) : "l"(p));
    return a;
}
__device__ __forceinline__ void cpa16(uint32_t saddr, const void* g) {
    asm volatile("cp.async.cg.shared.global [%0], [%1], 16;" :: "r"(saddr), "l"(g));
}
__device__ __forceinline__ void cp_commit() {
    asm volatile("cp.async.commit_group;" ::: "memory");
}
template <int N> __device__ __forceinline__ void cp_wait() {
    asm volatile("cp.async.wait_group %0;" :: "n"(N) : "memory");
}
__device__ __forceinline__ void ldsm4(uint32_t* r, uint32_t saddr) {
    asm volatile("ldmatrix.sync.aligned.m8n8.x4.shared.b16 {%0,%1,%2,%3}, [%4];"
                 : "=r"(r[0]), "=r"(r[1]), "=r"(r[2]), "=r"(r[3]) : "r"(saddr));
}
__device__ __forceinline__ void mma16(float* d, const uint32_t* a, uint32_t b0, uint32_t b1) {
    asm volatile(
        "mma.sync.aligned.m16n8k16.row.col.f32.f16.f16.f32 "
        "{%0,%1,%2,%3}, {%4,%5,%6,%7}, {%8,%9}, {%0,%1,%2,%3};"
        : "+f"(d[0]), "+f"(d[1]), "+f"(d[2]), "+f"(d[3])
        : "r"(a[0]), "r"(a[1]), "r"(a[2]), "r"(a[3]), "r"(b0), "r"(b1));
}
__device__ __forceinline__ uint32_t h2u(float a, float b) {
    __half2 h = __floats2half2_rn(a, b);
    return *(uint32_t*)&h;
}
__device__ __forceinline__ uint32_t ex2h2(uint32_t x) {
    uint32_t r;
    asm("ex2.approx.f16x2 %0, %1;" : "=r"(r) : "r"(x));
    return r;
}
__device__ __forceinline__ float ex2f(float x) {
    float r;
    asm("ex2.approx.f32 %0, %1;" : "=f"(r) : "f"(x));
    return r;
}

// =====================================================================
// Prepass 1: q/k/v fp32 -> fp16
// =====================================================================
__global__ __launch_bounds__(256) void cvt_kernel(
    const float* __restrict__ q, const float* __restrict__ k, const float* __restrict__ v) {
    int z = blockIdx.z;
    const float* src = (z == 0) ? q : (z == 1) ? k : v;
    __half* dst = (z == 0) ? g_hq : (z == 1) ? g_hk : g_hv;
    int nf4 = (M_TOTAL * D_MODEL) / 4;
    for (int i = blockIdx.x * blockDim.x + threadIdx.x; i < nf4; i += gridDim.x * blockDim.x) {
        float4 x = ((const float4*)src)[i];
        uint2 u = { h2u(x.x, x.y), h2u(x.z, x.w) };
        ((uint2*)dst)[i] = u;
    }
}

// Prepass 2: weights -> fp16, transposed: Wt[n][k] = h(W[k][n])
__global__ __launch_bounds__(256) void wtrans_kernel(
    const float* __restrict__ wq, const float* __restrict__ wk,
    const float* __restrict__ wv, const float* __restrict__ wo) {
    __shared__ float t[32][33];
    int z = blockIdx.z;
    const float* src = (z == 0) ? wq : (z == 1) ? wk : (z == 2) ? wv : wo;
    __half* dst = (z == 0) ? g_twq : (z == 1) ? g_twk : (z == 2) ? g_twv : g_two;
    int bk = blockIdx.x * 32, bn = blockIdx.y * 32;
    int tx = threadIdx.x & 31, ty = threadIdx.x >> 5;
#pragma unroll
    for (int i = 0; i < 4; i++)
        t[ty + 8 * i][tx] = src[(size_t)(bk + ty + 8 * i) * D_MODEL + bn + tx];
    __syncthreads();
#pragma unroll
    for (int i = 0; i < 4; i++)
        dst[(size_t)(bn + ty + 8 * i) * D_MODEL + bk + tx] = __float2half_rn(t[tx][ty + 8 * i]);
}

// =====================================================================
// fp16 GEMM: 128x128 tile, BK=64, 3 stages, LDSM + m16n8k16.
// =====================================================================
#define BK 64
#define NITER (D_MODEL / BK)
#define GPITCH 144
#define AB_OFF (128 * GPITCH)
#define STAGE_BYTES (2 * 128 * GPITCH)
#define NSTAGE 3
#define GEMM_SMEM_BYTES (NSTAGE * STAGE_BYTES)   // 110592

__device__ __forceinline__ void gemm_stage(const __half* __restrict__ A,
                                           const __half* __restrict__ Wt,
                                           int bm, int bn, int k0, int tid, uint32_t sb) {
#pragma unroll
    for (int t = 0; t < 4; t++) {
        int id = tid + t * 256;
        int row = id >> 3, ch = id & 7;
        cpa16(sb + (uint32_t)(row * GPITCH + ch * 16),
              A + (size_t)(bm + row) * D_MODEL + k0 + ch * 8);
    }
#pragma unroll
    for (int t = 0; t < 4; t++) {
        int id = tid + t * 256;
        int row = id >> 3, ch = id & 7;
        cpa16(sb + AB_OFF + (uint32_t)(row * GPITCH + ch * 16),
              Wt + (size_t)(bn + row) * D_MODEL + k0 + ch * 8);
    }
    cp_commit();
}

// mode 0: fp32 flat; mode 1: fp16 head-split [bh][s][d] (scaled by scl); mode 2: fp16 V^T [bh][d][s]
__device__ __forceinline__ void gemm_tc(const __half* __restrict__ A,
                                        const __half* __restrict__ Wt,
                                        const float* __restrict__ bias,
                                        float* __restrict__ dstf, __half* __restrict__ dsth,
                                        int mode, float scl) {
    extern __shared__ uint32_t sm[];
    const uint32_t smb = smem_u32(sm);

    const int tid = threadIdx.x;
    const int lane = tid & 31, w = tid >> 5;
    const int g = lane >> 2, tig = lane & 3;
    const int wm = w & 3, wn = w >> 2;
    const int bm = blockIdx.y * 128, bn = blockIdx.x * 128;

    const int t8 = lane >> 3, lr = lane & 7;
    uint32_t aoff[2];
#pragma unroll
    for (int am = 0; am < 2; am++)
        aoff[am] = (uint32_t)((wm * 32 + am * 16 + (t8 & 1) * 8 + lr) * GPITCH + (t8 >> 1) * 16);
    uint32_t boff[4];
#pragma unroll
    for (int p = 0; p < 4; p++)
        boff[p] = AB_OFF +
            (uint32_t)((wn * 64 + p * 16 + (t8 >> 1) * 8 + lr) * GPITCH + (t8 & 1) * 16);

    float acc[2][8][4];
#pragma unroll
    for (int i = 0; i < 2; i++)
#pragma unroll
        for (int j = 0; j < 8; j++)
#pragma unroll
            for (int r = 0; r < 4; r++) acc[i][j][r] = 0.0f;

    gemm_stage(A, Wt, bm, bn, 0, tid, smb);
    gemm_stage(A, Wt, bm, bn, BK, tid, smb + STAGE_BYTES);

    int sidx = 0;
#pragma unroll 1
    for (int j = 0; j < NITER; j++) {
        if (j == NITER - 1) cp_wait<0>(); else cp_wait<1>();
        __syncthreads();
        uint32_t sb = smb + sidx * STAGE_BYTES;

#pragma unroll
        for (int ks = 0; ks < 4; ks++) {
            uint32_t af[2][4];
            ldsm4(af[0], sb + aoff[0] + ks * 32);
            ldsm4(af[1], sb + aoff[1] + ks * 32);
#pragma unroll
            for (int p = 0; p < 4; p++) {
                uint32_t bq[4];
                ldsm4(bq, sb + boff[p] + ks * 32);
                mma16(acc[0][2 * p],     af[0], bq[0], bq[1]);
                mma16(acc[0][2 * p + 1], af[0], bq[2], bq[3]);
                mma16(acc[1][2 * p],     af[1], bq[0], bq[1]);
                mma16(acc[1][2 * p + 1], af[1], bq[2], bq[3]);
            }
        }

        if (j + 2 < NITER) {
            int ns = sidx + 2; if (ns >= NSTAGE) ns -= NSTAGE;
            gemm_stage(A, Wt, bm, bn, (j + 2) * BK, tid, smb + ns * STAGE_BYTES);
        }
        sidx++; if (sidx == NSTAGE) sidx = 0;
    }

#pragma unroll
    for (int am = 0; am < 2; am++)
#pragma unroll
        for (int an = 0; an < 8; an++) {
            int r = bm + wm * 32 + am * 16 + g;
            int n = bn + wn * 64 + an * 8 + 2 * tig;
            float b0 = bias[n], b1 = bias[n + 1];
            float c0 = (acc[am][an][0] + b0) * scl, c1 = (acc[am][an][1] + b1) * scl;
            float c2 = (acc[am][an][2] + b0) * scl, c3 = (acc[am][an][3] + b1) * scl;
            if (mode == 0) {
                float2 v0 = { c0, c1 }, v1 = { c2, c3 };
                *(float2*)(dstf + (size_t)r * D_MODEL + n) = v0;
                *(float2*)(dstf + (size_t)(r + 8) * D_MODEL + n) = v1;
            } else if (mode == 1) {
                int h = n >> 6, d = n & 63;
                int b = r >> 11, s = r & 2047;
                *(uint32_t*)(dsth + ((((size_t)b * N_HEAD + h) * SEQ + s) << 6) + d) = h2u(c0, c1);
                int s1 = (r + 8) & 2047, b1i = (r + 8) >> 11;
                *(uint32_t*)(dsth + ((((size_t)b1i * N_HEAD + h) * SEQ + s1) << 6) + d) = h2u(c2, c3);
            } else {
                int h = n >> 6, d = n & 63;
                int b = r >> 11, s = r & 2047;
                size_t base = ((size_t)(b * N_HEAD + h) * HEAD_DIM + d) * SEQ;
                dsth[base + s]       = __float2half_rn(c0);
                dsth[base + SEQ + s] = __float2half_rn(c1);
                int s1 = (r + 8) & 2047, b1i = (r + 8) >> 11;
                size_t base1 = ((size_t)(b1i * N_HEAD + h) * HEAD_DIM + d) * SEQ;
                dsth[base1 + s1]       = __float2half_rn(c2);
                dsth[base1 + SEQ + s1] = __float2half_rn(c3);
            }
        }
}

__global__ __launch_bounds__(256, 2)
void qkv_gemm_kernel(const float* __restrict__ bq, const float* __restrict__ bk,
                     const float* __restrict__ bv) {
    int z = blockIdx.z;
    const __half* A  = (z == 0) ? g_hq  : (z == 1) ? g_hk  : g_hv;
    const __half* Wt = (z == 0) ? g_twq : (z == 1) ? g_twk : g_twv;
    const float* b   = (z == 0) ? bq : (z == 1) ? bk : bv;
    __half* dsth     = (z == 0) ? g_qh : (z == 1) ? g_kh : g_vt;
    gemm_tc(A, Wt, b, nullptr, dsth, (z == 2) ? 2 : 1, (z == 0) ? SCALE_LOG2E : 1.0f);
}

__global__ __launch_bounds__(256, 2)
void out_gemm_kernel(const float* __restrict__ bo, float* __restrict__ out) {
    gemm_tc(g_attn, g_two, bo, out, nullptr, 0, 1.0f);
}

// =====================================================================
// Flash attention: register-resident P, f16x2 exp2, MMA row-sums.
// CTA: 128 q of one (b,h), 8 warps x 16 q. 64-key tiles, 3-stage K/V.
// =====================================================================
#define APITCH 144
#define NT (SEQ / 64)
#define ATTN_SMEM_BYTES ((128 + 3 * 64 + 3 * 64) * APITCH)   // 73728

__device__ __forceinline__ void attn_stage(const __half* Kg, const __half* Vg, int kt,
                                           int tid, uint32_t ksb, uint32_t vsb) {
#pragma unroll
    for (int t = 0; t < 2; t++) {
        int id = tid + t * 256;
        int row = id >> 3, ch = id & 7;
        cpa16(ksb + (uint32_t)(row * APITCH + ch * 16),
              Kg + (size_t)(kt * 64 + row) * 64 + ch * 8);
        cpa16(vsb + (uint32_t)(row * APITCH + ch * 16),
              Vg + (size_t)row * SEQ + kt * 64 + ch * 8);
    }
    cp_commit();
}

__global__ __launch_bounds__(256, 2) void attn_kernel() {
    extern __shared__ uint32_t sm[];
    const uint32_t smb = smem_u32(sm);
    const uint32_t qsb = smb;
    uint32_t ksb[3], vsb[3];
#pragma unroll
    for (int i = 0; i < 3; i++) {
        ksb[i] = smb + (128 + i * 64) * APITCH;
        vsb[i] = smb + (128 + 192 + i * 64) * APITCH;
    }

    const int tid = threadIdx.x;
    const int lane = tid & 31, w = tid >> 5;
    const int g = lane >> 2, tig = lane & 3;
    const int qb = blockIdx.x, bh = blockIdx.y;
    const int batch = bh >> 4, h = bh & 15;

    const __half* Qg = g_qh + ((size_t)bh * SEQ + qb * 128) * 64;
    const __half* Kg = g_kh + (size_t)bh * SEQ * 64;
    const __half* Vg = g_vt + (size_t)bh * HEAD_DIM * SEQ;

    const int t8 = lane >> 3, lr = lane & 7;
    const uint32_t qoff = (uint32_t)((16 * w + (t8 & 1) * 8 + lr) * APITCH + (t8 >> 1) * 16);
    uint32_t bofs[4];
#pragma unroll
    for (int p = 0; p < 4; p++)
        bofs[p] = (uint32_t)((p * 16 + (t8 >> 1) * 8 + lr) * APITCH + (t8 & 1) * 16);

    // prologue: group1 = Q + K0 + V0 ; group2 = K1 + V1
#pragma unroll
    for (int t = 0; t < 4; t++) {
        int id = tid + t * 256;
        int row = id >> 3, ch = id & 7;
        cpa16(qsb + (uint32_t)(row * APITCH + ch * 16), Qg + row * 64 + ch * 8);
    }
#pragma unroll
    for (int t = 0; t < 2; t++) {
        int id = tid + t * 256;
        int row = id >> 3, ch = id & 7;
        cpa16(ksb[0] + (uint32_t)(row * APITCH + ch * 16), Kg + (size_t)row * 64 + ch * 8);
        cpa16(vsb[0] + (uint32_t)(row * APITCH + ch * 16), Vg + (size_t)row * SEQ + ch * 8);
    }
    cp_commit();
    attn_stage(Kg, Vg, 1, tid, ksb[1], vsb[1]);

    uint32_t qf[4][4];
    float o[8][4], lacc[4];
#pragma unroll
    for (int a = 0; a < 8; a++)
#pragma unroll
        for (int r = 0; r < 4; r++) o[a][r] = 0.0f;
#pragma unroll
    for (int r = 0; r < 4; r++) lacc[r] = 0.0f;
    float m0 = -CUDART_INF_F, m1 = -CUDART_INF_F;
    const uint32_t ONES = 0x3C003C00u;   // half2(1, 1)
    const int r0 = 16 * w + g;

    int sidx = 0;
#pragma unroll 1
    for (int kt = 0; kt < NT; kt++) {
        if (kt == NT - 1) cp_wait<0>(); else cp_wait<1>();
        __syncthreads();

        if (kt == 0) {
#pragma unroll
            for (int ks = 0; ks < 4; ks++) ldsm4(qf[ks], qsb + qoff + ks * 32);
        }

        // S = Q @ K^T  (already in log2 domain; Q pre-scaled)
        float s[8][4];
#pragma unroll
        for (int a = 0; a < 8; a++)
#pragma unroll
            for (int r = 0; r < 4; r++) s[a][r] = 0.0f;
#pragma unroll
        for (int ks = 0; ks < 4; ks++) {
#pragma unroll
            for (int p = 0; p < 4; p++) {
                uint32_t bq[4];
                ldsm4(bq, ksb[sidx] + bofs[p] + ks * 32);
                mma16(s[2 * p],     qf[ks], bq[0], bq[1]);
                mma16(s[2 * p + 1], qf[ks], bq[2], bq[3]);
            }
        }

        // online softmax: max
        float mx0 = -CUDART_INF_F, mx1 = -CUDART_INF_F;
#pragma unroll
        for (int an = 0; an < 8; an++) {
            mx0 = fmaxf(mx0, fmaxf(s[an][0], s[an][1]));
            mx1 = fmaxf(mx1, fmaxf(s[an][2], s[an][3]));
        }
        mx0 = fmaxf(mx0, __shfl_xor_sync(0xffffffffu, mx0, 1));
        mx0 = fmaxf(mx0, __shfl_xor_sync(0xffffffffu, mx0, 2));
        mx1 = fmaxf(mx1, __shfl_xor_sync(0xffffffffu, mx1, 1));
        mx1 = fmaxf(mx1, __shfl_xor_sync(0xffffffffu, mx1, 2));
        float mn0 = fmaxf(m0, mx0), mn1 = fmaxf(m1, mx1);
        float al0 = ex2f(m0 - mn0), al1 = ex2f(m1 - mn1);
        m0 = mn0; m1 = mn1;

        // P fragments directly in registers (f16x2 exp2)
        uint32_t pf[4][4];
#pragma unroll
        for (int ks = 0; ks < 4; ks++) {
            pf[ks][0] = ex2h2(h2u(s[2 * ks][0] - mn0,     s[2 * ks][1] - mn0));
            pf[ks][1] = ex2h2(h2u(s[2 * ks][2] - mn1,     s[2 * ks][3] - mn1));
            pf[ks][2] = ex2h2(h2u(s[2 * ks + 1][0] - mn0, s[2 * ks + 1][1] - mn0));
            pf[ks][3] = ex2h2(h2u(s[2 * ks + 1][2] - mn1, s[2 * ks + 1][3] - mn1));
        }

        // rescale accumulators, then l += P @ ones and O += P @ V
        lacc[0] *= al0; lacc[1] *= al0; lacc[2] *= al1; lacc[3] *= al1;
#pragma unroll
        for (int an = 0; an < 8; an++) {
            o[an][0] *= al0; o[an][1] *= al0;
            o[an][2] *= al1; o[an][3] *= al1;
        }
#pragma unroll
        for (int ks = 0; ks < 4; ks++) {
            mma16(lacc, pf[ks], ONES, ONES);
#pragma unroll
            for (int p = 0; p < 4; p++) {
                uint32_t bv[4];
                ldsm4(bv, vsb[sidx] + bofs[p] + ks * 32);
                mma16(o[2 * p],     pf[ks], bv[0], bv[1]);
                mma16(o[2 * p + 1], pf[ks], bv[2], bv[3]);
            }
        }

        if (kt + 2 < NT) {
            int ns = sidx + 2; if (ns >= 3) ns -= 3;
            attn_stage(Kg, Vg, kt + 2, tid, ksb[ns], vsb[ns]);
        }
        sidx++; if (sidx == 3) sidx = 0;
    }

    // finalize: lacc holds complete row sums (all quad lanes identical)
    float inv0 = 1.0f / lacc[0], inv1 = 1.0f / lacc[2];

    int mrow = batch * SEQ + qb * 128 + r0;
#pragma unroll
    for (int an = 0; an < 8; an++) {
        int d = an * 8 + 2 * tig;
        *(uint32_t*)(g_attn + (size_t)mrow * D_MODEL + h * 64 + d) =
            h2u(o[an][0] * inv0, o[an][1] * inv0);
        *(uint32_t*)(g_attn + (size_t)(mrow + 8) * D_MODEL + h * 64 + d) =
            h2u(o[an][2] * inv1, o[an][3] * inv1);
    }
}

// ---------------------------------------------------------------------------
extern "C" void kernel_launch(void* const* d_in, const int* in_sizes, int n_in,
                              void* d_out, int out_size) {
    const float* q  = (const float*)d_in[0];
    const float* k  = (const float*)d_in[1];
    const float* v  = (const float*)d_in[2];
    const float* Wq = (const float*)d_in[3];
    const float* bq = (const float*)d_in[4];
    const float* Wk = (const float*)d_in[5];
    const float* bk = (const float*)d_in[6];
    const float* Wv = (const float*)d_in[7];
    const float* bv = (const float*)d_in[8];
    const float* Wo = (const float*)d_in[9];
    const float* bo = (const float*)d_in[10];
    float* out = (float*)d_out;

    cudaFuncSetAttribute(qkv_gemm_kernel, cudaFuncAttributeMaxDynamicSharedMemorySize, GEMM_SMEM_BYTES);
    cudaFuncSetAttribute(out_gemm_kernel, cudaFuncAttributeMaxDynamicSharedMemorySize, GEMM_SMEM_BYTES);
    cudaFuncSetAttribute(attn_kernel,     cudaFuncAttributeMaxDynamicSharedMemorySize, ATTN_SMEM_BYTES);

    dim3 g_cvt(512, 1, 3);
    cvt_kernel<<<g_cvt, 256>>>(q, k, v);

    dim3 g_wt(D_MODEL / 32, D_MODEL / 32, 4);
    wtrans_kernel<<<g_wt, 256>>>(Wq, Wk, Wv, Wo);

    dim3 g_qkv(D_MODEL / 128, M_TOTAL / 128, 3);   // (8, 32, 3)
    qkv_gemm_kernel<<<g_qkv, 256, GEMM_SMEM_BYTES>>>(bq, bk, bv);

    dim3 g_att(SEQ / 128, BATCH * N_HEAD);         // (16, 32)
    attn_kernel<<<g_att, 256, ATTN_SMEM_BYTES>>>();

    dim3 g_out(D_MODEL / 128, M_TOTAL / 128);      // (8, 32)
    out_gemm_kernel<<<g_out, 256, GEMM_SMEM_BYTES>>>(bo, out);
}